// round 9
// baseline (speedup 1.0000x reference)
#include <cuda_runtime.h>
#include <math.h>

// ---------------------------------------------------------------------------
// Problem constants
// ---------------------------------------------------------------------------
#define BATCH      8
#define STRIDE_F   32.0f
#define N_CELLS    196         // 14*14
#define WS_GRID    14
#define NUM_CLS    20
#define HEAD_OUT   25          // 1 + 20 + 4
#define CONF_TH    0.01f
#define NMS_TH     0.5f

// ---------------------------------------------------------------------------
// Scratch (static __device__ arrays: allocation-free, capture-safe).
// Ping-pong aliasing, safe under sequential default-stream execution.
// ---------------------------------------------------------------------------
__device__ float g_bufA[8L * 64 * 224 * 224];    // 102.8 MB
__device__ float g_bufB[8L * 128 * 112 * 112];   //  51.4 MB
__device__ float g_pred [8 * HEAD_OUT * N_CELLS];
__device__ float g_boxes[8 * N_CELLS * 4];
__device__ float g_cls  [8 * N_CELLS * NUM_CLS];

// ---------------------------------------------------------------------------
// 3x3 stride-2 conv + ReLU, SAME padding (JAX: pad_lo=0, pad_hi=1).
//
// v5: loader stall/issue-economy rework on top of the v4 structure.
//  - Tile: NCO co x (4 rows x 16 cols); 128 threads; thread = NCO/8 co x 4 r.
//  - Loaders FULLY UNROLLED with per-iteration independent addresses
//    (tid + 128*i, constant divisors) so ptxas batches the LDGs (MLP ~ iter
//    count instead of 1) -> the per-chunk loader wall drops from ~19 L2
//    round-trips to ~2.
//  - Weights loaded as float4 (9 LDG.128 per thread per chunk, was 36
//    scalar LDG) into co-contiguous smem [cc][k][NCO+4] -> LDS.128 feeds.
//  - NCO=32 variant (more CTAs, 8/SM) for the small L5 layer.
//  - Inputs de-interleaved even/odd columns: stride-2 -> unit-stride,
//    conflict-free broadcast LDS. All inner-loop addresses [base + imm].
// ---------------------------------------------------------------------------
template<int CIN, int COUT, int HIN, int WIN, int NCO>
__global__ __launch_bounds__(128, (NCO == 64 ? 6 : 8))
void conv3x3s2_relu(const float* __restrict__ in,
                    const float* __restrict__ w,
                    float* __restrict__ out)
{
    constexpr int HOUT = HIN / 2;
    constexpr int WOUT = WIN / 2;
    constexpr int CHUNK = (CIN % 8 == 0) ? 8 : CIN;   // 8, or 3 for layer 1
    constexpr int NTX  = (WOUT + 15) / 16;
    constexpr int COT  = NCO / 8;                     // co per thread (8 or 4)
    constexpr int WPAD = NCO + 4;                     // smem weight row stride
    constexpr int TIN  = CHUNK * 9 * 33;              // input tile elements

    const int bx  = blockIdx.x % NTX;
    const int by  = blockIdx.x / NTX;
    const int ox0 = bx * 16;
    const int oy0 = by * 4;
    const int co0 = blockIdx.y * NCO;
    const int b   = blockIdx.z;

    __shared__ float s_even[CHUNK][9][17];                 // even input cols
    __shared__ float s_odd [CHUNK][9][16];                 // odd  input cols
    __shared__ __align__(16) float s_w[CHUNK][9][WPAD];    // [cc][k][co]

    const int tid = threadIdx.x;   // 0..127
    const int tc  = tid >> 4;      // 0..7  -> co = co0 + tc*COT ...
    const int tp  = tid & 15;      // 0..15 -> output column within tile

    float acc[COT][4] = {};        // [co][row]

    const float* in_b = in + (size_t)b * CIN * HIN * WIN;
    const float* wg   = w + (size_t)co0 * CIN * 9;

    for (int ci0 = 0; ci0 < CIN; ci0 += CHUNK) {
        __syncthreads();   // protect smem from previous iteration's readers

        // ---- input tile: CHUNK channels x 9 rows x 33 cols.
        //      Fully unrolled; independent addresses -> batched LDGs. ----
        {
            const float* src = in_b + (size_t)ci0 * HIN * WIN;
            constexpr int ITERI = (TIN + 127) / 128;
#pragma unroll
            for (int i = 0; i < ITERI; i++) {
                const int idx = tid + i * 128;
                if ((TIN % 128 == 0) || (idx < TIN)) {
                    const int cc  = idx / 297;           // 9*33
                    const int rem = idx - cc * 297;
                    const int ly  = rem / 33;
                    const int lx  = rem - ly * 33;
                    const int iy  = 2 * oy0 + ly;        // pad_lo = 0
                    const int ix  = 2 * ox0 + lx;
                    float v = 0.0f;
                    if (iy < HIN && ix < WIN)
                        v = src[(size_t)cc * HIN * WIN + (size_t)iy * WIN + ix];
                    if (lx & 1) s_odd [cc][ly][lx >> 1] = v;
                    else        s_even[cc][ly][lx >> 1] = v;
                }
            }
        }

        // ---- weights -> smem [cc*9+k][co] (co-contiguous) ----
        {
            float* swf = &s_w[0][0][0];
            if constexpr ((CHUNK * 9) % 4 == 0) {
                // float4 path: CHUNK==8 -> 18 float4 per co
                constexpr int F4PC = CHUNK * 9 / 4;      // 18
                constexpr int NF4  = NCO * F4PC;
                constexpr int ITERW = (NF4 + 127) / 128;
#pragma unroll
                for (int i = 0; i < ITERW; i++) {
                    const int idx4 = tid + i * 128;
                    if ((NF4 % 128 == 0) || (idx4 < NF4)) {
                        const int co = idx4 / F4PC;
                        const int r4 = idx4 - co * F4PC;
                        const float4 t = *reinterpret_cast<const float4*>(
                            wg + (size_t)co * CIN * 9 + ci0 * 9 + r4 * 4);
                        float* d = swf + (r4 * 4) * WPAD + co;
                        d[0 * WPAD] = t.x;
                        d[1 * WPAD] = t.y;
                        d[2 * WPAD] = t.z;
                        d[3 * WPAD] = t.w;
                    }
                }
            } else {
                // scalar path (L1: CHUNK==3 -> 27 per co)
                constexpr int NE = NCO * CHUNK * 9;
                constexpr int ITERW = (NE + 127) / 128;
#pragma unroll
                for (int i = 0; i < ITERW; i++) {
                    const int idx = tid + i * 128;
                    if ((NE % 128 == 0) || (idx < NE)) {
                        const int co  = idx / (CHUNK * 9);
                        const int rem = idx - co * (CHUNK * 9);
                        swf[rem * WPAD + co] =
                            wg[(size_t)co * CIN * 9 + ci0 * 9 + rem];
                    }
                }
            }
        }
        __syncthreads();

        // ---- compute: direct float4/scalar feeds, no staging arrays ----
        const float* pe = &s_even[0][0][0] + tp;
        const float* po = &s_odd [0][0][0] + tp;
        const float* pw = &s_w[0][0][0] + tc * COT;

#pragma unroll 1
        for (int cc = 0; cc < CHUNK; cc++) {
#pragma unroll
            for (int ky = 0; ky < 3; ky++) {
#pragma unroll
                for (int kx = 0; kx < 3; kx++) {
                    const int kp = ky * 3 + kx;
                    const float4 wa = *reinterpret_cast<const float4*>(pw + kp * WPAD);
                    float4 wb;
                    if constexpr (COT == 8)
                        wb = *reinterpret_cast<const float4*>(pw + kp * WPAD + 4);
#pragma unroll
                    for (int r = 0; r < 4; r++) {
                        const int ly = 2 * r + ky;
                        const float iv = (kx == 1) ? po[ly * 16]
                                                   : pe[ly * 17 + (kx >> 1)];
                        acc[0][r] = fmaf(wa.x, iv, acc[0][r]);
                        acc[1][r] = fmaf(wa.y, iv, acc[1][r]);
                        acc[2][r] = fmaf(wa.z, iv, acc[2][r]);
                        acc[3][r] = fmaf(wa.w, iv, acc[3][r]);
                        if constexpr (COT == 8) {
                            acc[4][r] = fmaf(wb.x, iv, acc[4][r]);
                            acc[5][r] = fmaf(wb.y, iv, acc[5][r]);
                            acc[6][r] = fmaf(wb.z, iv, acc[6][r]);
                            acc[7][r] = fmaf(wb.w, iv, acc[7][r]);
                        }
                    }
                }
            }
            pe += 9 * 17;     // 153
            po += 9 * 16;     // 144
            pw += 9 * WPAD;
        }
    }

    // ---- epilogue: ReLU + store ----
    float* out_b = out + (size_t)b * COUT * HOUT * WOUT;
    const int ox = ox0 + tp;
    if (ox < WOUT) {
#pragma unroll
        for (int j = 0; j < COT; j++) {
            const int co = co0 + tc * COT + j;
#pragma unroll
            for (int r = 0; r < 4; r++) {
                const int oy = oy0 + r;
                if (oy < HOUT)
                    out_b[((size_t)co * HOUT + oy) * WOUT + ox] = fmaxf(acc[j][r], 0.0f);
            }
        }
    }
}

// ---------------------------------------------------------------------------
// 1x1 head conv: pred[b][o][p] = sum_ci h5[b][ci][p] * w[o][ci]
// ---------------------------------------------------------------------------
__global__ void yolo_head_kernel(const float* __restrict__ h5,
                                 const float* __restrict__ w,
                                 float* __restrict__ pred)
{
    const int b = blockIdx.x;
    const int o = blockIdx.y;
    const int p = threadIdx.x;
    if (p >= N_CELLS) return;
    const float* hb = h5 + (size_t)b * 512 * N_CELLS;
    const float* wo = w + o * 512;
    float s = 0.0f;
#pragma unroll 8
    for (int ci = 0; ci < 512; ci++)
        s = fmaf(hb[ci * N_CELLS + p], wo[ci], s);
    pred[(b * HEAD_OUT + o) * N_CELLS + p] = s;
}

// ---------------------------------------------------------------------------
// Decode: sigmoid conf, softmax*conf class scores, box decode + clip.
// ---------------------------------------------------------------------------
__global__ void yolo_decode_kernel(const float* __restrict__ pred,
                                   float* __restrict__ boxes,
                                   float* __restrict__ cls,
                                   float* __restrict__ out)
{
    const int b = blockIdx.x;
    const int p = threadIdx.x;
    if (p >= N_CELLS) return;
    const float* pb = pred + (size_t)b * HEAD_OUT * N_CELLS;

    float conf = 1.0f / (1.0f + expf(-pb[p]));

    float v[NUM_CLS];
    float m = -1e30f;
#pragma unroll
    for (int c = 0; c < NUM_CLS; c++) {
        v[c] = pb[(1 + c) * N_CELLS + p];
        m = fmaxf(m, v[c]);
    }
    float s = 0.0f;
#pragma unroll
    for (int c = 0; c < NUM_CLS; c++) { v[c] = expf(v[c] - m); s += v[c]; }
    float inv = conf / s;

    float tx = pb[21 * N_CELLS + p];
    float ty = pb[22 * N_CELLS + p];
    float tw = pb[23 * N_CELLS + p];
    float th = pb[24 * N_CELLS + p];

    float gx = (float)(p % WS_GRID);
    float gy = (float)(p / WS_GRID);
    float cx = (1.0f / (1.0f + expf(-tx)) + gx) * STRIDE_F;
    float cy = (1.0f / (1.0f + expf(-ty)) + gy) * STRIDE_F;
    float bw = expf(tw) * STRIDE_F;
    float bh = expf(th) * STRIDE_F;

    float x1 = (cx - bw * 0.5f) / 448.0f;
    float y1 = (cy - bh * 0.5f) / 448.0f;
    float x2 = (cx + bw * 0.5f) / 448.0f;
    float y2 = (cy + bh * 0.5f) / 448.0f;
    x1 = fminf(fmaxf(x1, 0.0f), 1.0f);
    y1 = fminf(fmaxf(y1, 0.0f), 1.0f);
    x2 = fminf(fmaxf(x2, 0.0f), 1.0f);
    y2 = fminf(fmaxf(y2, 0.0f), 1.0f);

    const int row = b * N_CELLS + p;
    boxes[row * 4 + 0] = x1;
    boxes[row * 4 + 1] = y1;
    boxes[row * 4 + 2] = x2;
    boxes[row * 4 + 3] = y2;
    out[row * 24 + 0] = x1;
    out[row * 24 + 1] = y1;
    out[row * 24 + 2] = x2;
    out[row * 24 + 3] = y2;
#pragma unroll
    for (int c = 0; c < NUM_CLS; c++)
        cls[row * NUM_CLS + c] = v[c] * inv;
}

// ---------------------------------------------------------------------------
// Per-(batch, class) greedy NMS. One block per problem.
// Stable descending rank (== stable argsort of -scores), then 196
// barrier-stepped suppression iterations (only kept boxes suppress).
// ---------------------------------------------------------------------------
__global__ void yolo_nms_kernel(const float* __restrict__ boxes,
                                const float* __restrict__ cls,
                                float* __restrict__ out)
{
    const int c = blockIdx.x;   // class
    const int b = blockIdx.y;   // batch
    const int t = threadIdx.x;

    __shared__ float ss[N_CELLS];
    __shared__ float sx1[N_CELLS], sy1[N_CELLS], sx2[N_CELLS], sy2[N_CELLS];
    __shared__ float sa[N_CELLS];
    __shared__ int   sorder[N_CELLS];
    __shared__ int   skeep[N_CELLS];

    if (t < N_CELLS) {
        const int row = b * N_CELLS + t;
        ss[t] = cls[row * NUM_CLS + c];
        float x1 = boxes[row * 4 + 0];
        float y1 = boxes[row * 4 + 1];
        float x2 = boxes[row * 4 + 2];
        float y2 = boxes[row * 4 + 3];
        sx1[t] = x1; sy1[t] = y1; sx2[t] = x2; sy2[t] = y2;
        sa[t] = fmaxf(x2 - x1, 0.0f) * fmaxf(y2 - y1, 0.0f);
    }
    __syncthreads();

    if (t < N_CELLS) {
        float sp = ss[t];
        int r = 0;
        for (int q = 0; q < N_CELLS; q++) {
            float sq = ss[q];
            r += (sq > sp) || (sq == sp && q < t);
        }
        sorder[r] = t;
        skeep[r]  = (sp > CONF_TH) ? 1 : 0;
    }
    __syncthreads();

    int pj = 0;
    float bx1 = 0.f, by1 = 0.f, bx2 = 0.f, by2 = 0.f, ba = 0.f;
    if (t < N_CELLS) {
        pj  = sorder[t];
        bx1 = sx1[pj]; by1 = sy1[pj]; bx2 = sx2[pj]; by2 = sy2[pj]; ba = sa[pj];
    }

    for (int i = 0; i < N_CELLS - 1; i++) {
        if (skeep[i]) {
            int pi = sorder[i];
            float ax1 = sx1[pi], ay1 = sy1[pi];
            float ax2 = sx2[pi], ay2 = sy2[pi];
            float aa  = sa[pi];
            if (t < N_CELLS && t > i && skeep[t]) {
                float ix1 = fmaxf(ax1, bx1), iy1 = fmaxf(ay1, by1);
                float ix2 = fminf(ax2, bx2), iy2 = fminf(ay2, by2);
                float inter = fmaxf(ix2 - ix1, 0.0f) * fmaxf(iy2 - iy1, 0.0f);
                float iou = inter / (aa + ba - inter + 1e-14f);
                if (iou > NMS_TH) skeep[t] = 0;
            }
        }
        __syncthreads();
    }

    if (t < N_CELLS) {
        const int row = b * N_CELLS + pj;
        out[row * 24 + 4 + c] = ss[pj] * (skeep[t] ? 1.0f : 0.0f);
    }
}

// ---------------------------------------------------------------------------
// Launch
// ---------------------------------------------------------------------------
extern "C" void kernel_launch(void* const* d_in, const int* in_sizes, int n_in,
                              void* d_out, int out_size)
{
    const float* x  = (const float*)d_in[0];
    const float* w1 = (const float*)d_in[1];
    const float* w2 = (const float*)d_in[2];
    const float* w3 = (const float*)d_in[3];
    const float* w4 = (const float*)d_in[4];
    const float* w5 = (const float*)d_in[5];
    const float* wh = (const float*)d_in[6];
    float* out = (float*)d_out;

    float *bufA, *bufB, *pred, *boxes, *cls;
    cudaGetSymbolAddress((void**)&bufA, g_bufA);
    cudaGetSymbolAddress((void**)&bufB, g_bufB);
    cudaGetSymbolAddress((void**)&pred, g_pred);
    cudaGetSymbolAddress((void**)&boxes, g_boxes);
    cudaGetSymbolAddress((void**)&cls, g_cls);

    float* h1 = bufA;
    float* h2 = bufB;
    float* h3 = bufA;
    float* h4 = bufB;
    float* h5 = bufA;

    {   // L1: 3 -> 64, 448 -> 224
        constexpr int NTX = (224 + 15) / 16, NTY = (224 + 3) / 4;
        conv3x3s2_relu<3, 64, 448, 448, 64>
            <<<dim3(NTX * NTY, 1, BATCH), 128>>>(x, w1, h1);
    }
    {   // L2: 64 -> 128, 224 -> 112
        constexpr int NTX = (112 + 15) / 16, NTY = (112 + 3) / 4;
        conv3x3s2_relu<64, 128, 224, 224, 64>
            <<<dim3(NTX * NTY, 2, BATCH), 128>>>(h1, w2, h2);
    }
    {   // L3: 128 -> 256, 112 -> 56
        constexpr int NTX = (56 + 15) / 16, NTY = (56 + 3) / 4;
        conv3x3s2_relu<128, 256, 112, 112, 64>
            <<<dim3(NTX * NTY, 4, BATCH), 128>>>(h2, w3, h3);
    }
    {   // L4: 256 -> 512, 56 -> 28
        constexpr int NTX = (28 + 15) / 16, NTY = (28 + 3) / 4;
        conv3x3s2_relu<256, 512, 56, 56, 64>
            <<<dim3(NTX * NTY, 8, BATCH), 128>>>(h3, w4, h4);
    }
    {   // L5: 512 -> 512, 28 -> 14  (NCO=32 -> 512 CTAs for parallelism)
        constexpr int NTX = (14 + 15) / 16, NTY = (14 + 3) / 4;
        conv3x3s2_relu<512, 512, 28, 28, 32>
            <<<dim3(NTX * NTY, 16, BATCH), 128>>>(h4, w5, h5);
    }

    yolo_head_kernel<<<dim3(BATCH, HEAD_OUT), 224>>>(h5, wh, pred);
    yolo_decode_kernel<<<BATCH, 224>>>(pred, boxes, cls, out);
    yolo_nms_kernel<<<dim3(NUM_CLS, BATCH), 224>>>(boxes, cls, out);
}

// round 10
// speedup vs baseline: 1.1635x; 1.1635x over previous
#include <cuda_runtime.h>
#include <math.h>

// ---------------------------------------------------------------------------
// Problem constants
// ---------------------------------------------------------------------------
#define BATCH      8
#define STRIDE_F   32.0f
#define N_CELLS    196         // 14*14
#define WS_GRID    14
#define NUM_CLS    20
#define HEAD_OUT   25          // 1 + 20 + 4
#define CONF_TH    0.01f
#define NMS_TH     0.5f

// ---------------------------------------------------------------------------
// Scratch (static __device__ arrays: allocation-free, capture-safe).
// Ping-pong aliasing, safe under sequential default-stream execution.
// ---------------------------------------------------------------------------
__device__ float g_bufA[8L * 64 * 224 * 224];    // 102.8 MB
__device__ float g_bufB[8L * 128 * 112 * 112];   //  51.4 MB
__device__ float g_pred [8 * HEAD_OUT * N_CELLS];
__device__ float g_boxes[8 * N_CELLS * 4];
__device__ float g_cls  [8 * N_CELLS * NUM_CLS];

// ---------------------------------------------------------------------------
// 3x3 stride-2 conv + ReLU, SAME padding (JAX: pad_lo=0, pad_hi=1).
//
// v6 = R8 structure (proven fastest) + three separable deltas:
//  - input loader: rolled loop with #pragma unroll 4 (MLP~4, no queue burst)
//  - weight loader: float4 loads, rolled loop (ALU cut, measured in R9)
//  - NCO template param; L5 uses NCO=32 for 2x CTA parallelism
//
// Tile: NCO co x (4 rows x 16 cols); 128 threads; thread = NCO/8 co x 4 rows.
// Weights staged co-contiguous ([cc][k][NCO+4]) -> LDS.128 feeds FMAs direct.
// Inputs de-interleaved even/odd columns: stride-2 -> unit-stride LDS,
// 16 distinct addrs/warp = conflict-free broadcast. Inner-loop smem
// addresses are all [base + immediate]; 3 pointer bumps per input channel.
// ---------------------------------------------------------------------------
template<int CIN, int COUT, int HIN, int WIN, int NCO>
__global__ __launch_bounds__(128, (NCO == 64 ? 6 : 8))
void conv3x3s2_relu(const float* __restrict__ in,
                    const float* __restrict__ w,
                    float* __restrict__ out)
{
    constexpr int HOUT = HIN / 2;
    constexpr int WOUT = WIN / 2;
    constexpr int CHUNK = (CIN % 8 == 0) ? 8 : CIN;   // 8, or 3 for layer 1
    constexpr int NTX  = (WOUT + 15) / 16;
    constexpr int COT  = NCO / 8;                     // co per thread (8 or 4)
    constexpr int WPAD = NCO + 4;                     // smem weight row stride
    constexpr int TIN  = CHUNK * 9 * 33;              // input tile elements

    const int bx  = blockIdx.x % NTX;
    const int by  = blockIdx.x / NTX;
    const int ox0 = bx * 16;
    const int oy0 = by * 4;
    const int co0 = blockIdx.y * NCO;
    const int b   = blockIdx.z;

    __shared__ float s_even[CHUNK][9][17];                 // even input cols
    __shared__ float s_odd [CHUNK][9][16];                 // odd  input cols
    __shared__ __align__(16) float s_w[CHUNK][9][WPAD];    // [cc][k][co]

    const int tid = threadIdx.x;   // 0..127
    const int tc  = tid >> 4;      // 0..7  -> co = co0 + tc*COT ...
    const int tp  = tid & 15;      // 0..15 -> output column within tile

    float acc[COT][4] = {};        // [co][row]

    const float* in_b = in + (size_t)b * CIN * HIN * WIN;
    const float* wg   = w + (size_t)co0 * CIN * 9;

    for (int ci0 = 0; ci0 < CIN; ci0 += CHUNK) {
        __syncthreads();   // protect smem from previous iteration's readers

        // ---- input tile: CHUNK channels x 9 rows x 33 cols (MLP~4) ----
        {
            const float* src = in_b + (size_t)ci0 * HIN * WIN;
#pragma unroll 4
            for (int idx = tid; idx < TIN; idx += 128) {
                const int cc  = idx / 297;           // 9*33
                const int rem = idx - cc * 297;
                const int ly  = rem / 33;
                const int lx  = rem - ly * 33;
                const int iy  = 2 * oy0 + ly;        // pad_lo = 0
                const int ix  = 2 * ox0 + lx;
                float v = 0.0f;
                if (iy < HIN && ix < WIN)
                    v = src[(size_t)cc * HIN * WIN + (size_t)iy * WIN + ix];
                if (lx & 1) s_odd [cc][ly][lx >> 1] = v;
                else        s_even[cc][ly][lx >> 1] = v;
            }
        }

        // ---- weights -> smem [cc*9+k][co] (co-contiguous) ----
        {
            float* swf = &s_w[0][0][0];
            if constexpr ((CHUNK * 9) % 4 == 0) {
                // float4 path: CHUNK==8 -> 18 float4 per co, rolled loop
                constexpr int F4PC = CHUNK * 9 / 4;      // 18
                constexpr int NF4  = NCO * F4PC;
#pragma unroll 3
                for (int idx4 = tid; idx4 < NF4; idx4 += 128) {
                    const int co = idx4 / F4PC;
                    const int r4 = idx4 - co * F4PC;
                    const float4 t = *reinterpret_cast<const float4*>(
                        wg + (size_t)co * CIN * 9 + ci0 * 9 + r4 * 4);
                    float* d = swf + (r4 * 4) * WPAD + co;
                    d[0 * WPAD] = t.x;
                    d[1 * WPAD] = t.y;
                    d[2 * WPAD] = t.z;
                    d[3 * WPAD] = t.w;
                }
            } else {
                // scalar path (L1: CHUNK==3 -> 27 per co), rolled loop
                constexpr int NE = NCO * CHUNK * 9;
#pragma unroll 4
                for (int idx = tid; idx < NE; idx += 128) {
                    const int co  = idx / (CHUNK * 9);
                    const int rem = idx - co * (CHUNK * 9);
                    swf[rem * WPAD + co] =
                        wg[(size_t)co * CIN * 9 + ci0 * 9 + rem];
                }
            }
        }
        __syncthreads();

        // ---- compute: direct float4/scalar feeds, no staging arrays ----
        const float* pe = &s_even[0][0][0] + tp;
        const float* po = &s_odd [0][0][0] + tp;
        const float* pw = &s_w[0][0][0] + tc * COT;

#pragma unroll 1
        for (int cc = 0; cc < CHUNK; cc++) {
#pragma unroll
            for (int ky = 0; ky < 3; ky++) {
#pragma unroll
                for (int kx = 0; kx < 3; kx++) {
                    const int kp = ky * 3 + kx;
                    const float4 wa = *reinterpret_cast<const float4*>(pw + kp * WPAD);
                    float4 wb;
                    if constexpr (COT == 8)
                        wb = *reinterpret_cast<const float4*>(pw + kp * WPAD + 4);
#pragma unroll
                    for (int r = 0; r < 4; r++) {
                        const int ly = 2 * r + ky;
                        const float iv = (kx == 1) ? po[ly * 16]
                                                   : pe[ly * 17 + (kx >> 1)];
                        acc[0][r] = fmaf(wa.x, iv, acc[0][r]);
                        acc[1][r] = fmaf(wa.y, iv, acc[1][r]);
                        acc[2][r] = fmaf(wa.z, iv, acc[2][r]);
                        acc[3][r] = fmaf(wa.w, iv, acc[3][r]);
                        if constexpr (COT == 8) {
                            acc[4][r] = fmaf(wb.x, iv, acc[4][r]);
                            acc[5][r] = fmaf(wb.y, iv, acc[5][r]);
                            acc[6][r] = fmaf(wb.z, iv, acc[6][r]);
                            acc[7][r] = fmaf(wb.w, iv, acc[7][r]);
                        }
                    }
                }
            }
            pe += 9 * 17;     // 153
            po += 9 * 16;     // 144
            pw += 9 * WPAD;
        }
    }

    // ---- epilogue: ReLU + store ----
    float* out_b = out + (size_t)b * COUT * HOUT * WOUT;
    const int ox = ox0 + tp;
    if (ox < WOUT) {
#pragma unroll
        for (int j = 0; j < COT; j++) {
            const int co = co0 + tc * COT + j;
#pragma unroll
            for (int r = 0; r < 4; r++) {
                const int oy = oy0 + r;
                if (oy < HOUT)
                    out_b[((size_t)co * HOUT + oy) * WOUT + ox] = fmaxf(acc[j][r], 0.0f);
            }
        }
    }
}

// ---------------------------------------------------------------------------
// 1x1 head conv: pred[b][o][p] = sum_ci h5[b][ci][p] * w[o][ci]
// ---------------------------------------------------------------------------
__global__ void yolo_head_kernel(const float* __restrict__ h5,
                                 const float* __restrict__ w,
                                 float* __restrict__ pred)
{
    const int b = blockIdx.x;
    const int o = blockIdx.y;
    const int p = threadIdx.x;
    if (p >= N_CELLS) return;
    const float* hb = h5 + (size_t)b * 512 * N_CELLS;
    const float* wo = w + o * 512;
    float s = 0.0f;
#pragma unroll 8
    for (int ci = 0; ci < 512; ci++)
        s = fmaf(hb[ci * N_CELLS + p], wo[ci], s);
    pred[(b * HEAD_OUT + o) * N_CELLS + p] = s;
}

// ---------------------------------------------------------------------------
// Decode: sigmoid conf, softmax*conf class scores, box decode + clip.
// ---------------------------------------------------------------------------
__global__ void yolo_decode_kernel(const float* __restrict__ pred,
                                   float* __restrict__ boxes,
                                   float* __restrict__ cls,
                                   float* __restrict__ out)
{
    const int b = blockIdx.x;
    const int p = threadIdx.x;
    if (p >= N_CELLS) return;
    const float* pb = pred + (size_t)b * HEAD_OUT * N_CELLS;

    float conf = 1.0f / (1.0f + expf(-pb[p]));

    float v[NUM_CLS];
    float m = -1e30f;
#pragma unroll
    for (int c = 0; c < NUM_CLS; c++) {
        v[c] = pb[(1 + c) * N_CELLS + p];
        m = fmaxf(m, v[c]);
    }
    float s = 0.0f;
#pragma unroll
    for (int c = 0; c < NUM_CLS; c++) { v[c] = expf(v[c] - m); s += v[c]; }
    float inv = conf / s;

    float tx = pb[21 * N_CELLS + p];
    float ty = pb[22 * N_CELLS + p];
    float tw = pb[23 * N_CELLS + p];
    float th = pb[24 * N_CELLS + p];

    float gx = (float)(p % WS_GRID);
    float gy = (float)(p / WS_GRID);
    float cx = (1.0f / (1.0f + expf(-tx)) + gx) * STRIDE_F;
    float cy = (1.0f / (1.0f + expf(-ty)) + gy) * STRIDE_F;
    float bw = expf(tw) * STRIDE_F;
    float bh = expf(th) * STRIDE_F;

    float x1 = (cx - bw * 0.5f) / 448.0f;
    float y1 = (cy - bh * 0.5f) / 448.0f;
    float x2 = (cx + bw * 0.5f) / 448.0f;
    float y2 = (cy + bh * 0.5f) / 448.0f;
    x1 = fminf(fmaxf(x1, 0.0f), 1.0f);
    y1 = fminf(fmaxf(y1, 0.0f), 1.0f);
    x2 = fminf(fmaxf(x2, 0.0f), 1.0f);
    y2 = fminf(fmaxf(y2, 0.0f), 1.0f);

    const int row = b * N_CELLS + p;
    boxes[row * 4 + 0] = x1;
    boxes[row * 4 + 1] = y1;
    boxes[row * 4 + 2] = x2;
    boxes[row * 4 + 3] = y2;
    out[row * 24 + 0] = x1;
    out[row * 24 + 1] = y1;
    out[row * 24 + 2] = x2;
    out[row * 24 + 3] = y2;
#pragma unroll
    for (int c = 0; c < NUM_CLS; c++)
        cls[row * NUM_CLS + c] = v[c] * inv;
}

// ---------------------------------------------------------------------------
// Per-(batch, class) greedy NMS. One block per problem.
// Stable descending rank (== stable argsort of -scores), then 196
// barrier-stepped suppression iterations (only kept boxes suppress).
// ---------------------------------------------------------------------------
__global__ void yolo_nms_kernel(const float* __restrict__ boxes,
                                const float* __restrict__ cls,
                                float* __restrict__ out)
{
    const int c = blockIdx.x;   // class
    const int b = blockIdx.y;   // batch
    const int t = threadIdx.x;

    __shared__ float ss[N_CELLS];
    __shared__ float sx1[N_CELLS], sy1[N_CELLS], sx2[N_CELLS], sy2[N_CELLS];
    __shared__ float sa[N_CELLS];
    __shared__ int   sorder[N_CELLS];
    __shared__ int   skeep[N_CELLS];

    if (t < N_CELLS) {
        const int row = b * N_CELLS + t;
        ss[t] = cls[row * NUM_CLS + c];
        float x1 = boxes[row * 4 + 0];
        float y1 = boxes[row * 4 + 1];
        float x2 = boxes[row * 4 + 2];
        float y2 = boxes[row * 4 + 3];
        sx1[t] = x1; sy1[t] = y1; sx2[t] = x2; sy2[t] = y2;
        sa[t] = fmaxf(x2 - x1, 0.0f) * fmaxf(y2 - y1, 0.0f);
    }
    __syncthreads();

    if (t < N_CELLS) {
        float sp = ss[t];
        int r = 0;
        for (int q = 0; q < N_CELLS; q++) {
            float sq = ss[q];
            r += (sq > sp) || (sq == sp && q < t);
        }
        sorder[r] = t;
        skeep[r]  = (sp > CONF_TH) ? 1 : 0;
    }
    __syncthreads();

    int pj = 0;
    float bx1 = 0.f, by1 = 0.f, bx2 = 0.f, by2 = 0.f, ba = 0.f;
    if (t < N_CELLS) {
        pj  = sorder[t];
        bx1 = sx1[pj]; by1 = sy1[pj]; bx2 = sx2[pj]; by2 = sy2[pj]; ba = sa[pj];
    }

    for (int i = 0; i < N_CELLS - 1; i++) {
        if (skeep[i]) {
            int pi = sorder[i];
            float ax1 = sx1[pi], ay1 = sy1[pi];
            float ax2 = sx2[pi], ay2 = sy2[pi];
            float aa  = sa[pi];
            if (t < N_CELLS && t > i && skeep[t]) {
                float ix1 = fmaxf(ax1, bx1), iy1 = fmaxf(ay1, by1);
                float ix2 = fminf(ax2, bx2), iy2 = fminf(ay2, by2);
                float inter = fmaxf(ix2 - ix1, 0.0f) * fmaxf(iy2 - iy1, 0.0f);
                float iou = inter / (aa + ba - inter + 1e-14f);
                if (iou > NMS_TH) skeep[t] = 0;
            }
        }
        __syncthreads();
    }

    if (t < N_CELLS) {
        const int row = b * N_CELLS + pj;
        out[row * 24 + 4 + c] = ss[pj] * (skeep[t] ? 1.0f : 0.0f);
    }
}

// ---------------------------------------------------------------------------
// Launch
// ---------------------------------------------------------------------------
extern "C" void kernel_launch(void* const* d_in, const int* in_sizes, int n_in,
                              void* d_out, int out_size)
{
    const float* x  = (const float*)d_in[0];
    const float* w1 = (const float*)d_in[1];
    const float* w2 = (const float*)d_in[2];
    const float* w3 = (const float*)d_in[3];
    const float* w4 = (const float*)d_in[4];
    const float* w5 = (const float*)d_in[5];
    const float* wh = (const float*)d_in[6];
    float* out = (float*)d_out;

    float *bufA, *bufB, *pred, *boxes, *cls;
    cudaGetSymbolAddress((void**)&bufA, g_bufA);
    cudaGetSymbolAddress((void**)&bufB, g_bufB);
    cudaGetSymbolAddress((void**)&pred, g_pred);
    cudaGetSymbolAddress((void**)&boxes, g_boxes);
    cudaGetSymbolAddress((void**)&cls, g_cls);

    float* h1 = bufA;
    float* h2 = bufB;
    float* h3 = bufA;
    float* h4 = bufB;
    float* h5 = bufA;

    {   // L1: 3 -> 64, 448 -> 224
        constexpr int NTX = (224 + 15) / 16, NTY = (224 + 3) / 4;
        conv3x3s2_relu<3, 64, 448, 448, 64>
            <<<dim3(NTX * NTY, 1, BATCH), 128>>>(x, w1, h1);
    }
    {   // L2: 64 -> 128, 224 -> 112
        constexpr int NTX = (112 + 15) / 16, NTY = (112 + 3) / 4;
        conv3x3s2_relu<64, 128, 224, 224, 64>
            <<<dim3(NTX * NTY, 2, BATCH), 128>>>(h1, w2, h2);
    }
    {   // L3: 128 -> 256, 112 -> 56
        constexpr int NTX = (56 + 15) / 16, NTY = (56 + 3) / 4;
        conv3x3s2_relu<128, 256, 112, 112, 64>
            <<<dim3(NTX * NTY, 4, BATCH), 128>>>(h2, w3, h3);
    }
    {   // L4: 256 -> 512, 56 -> 28
        constexpr int NTX = (28 + 15) / 16, NTY = (28 + 3) / 4;
        conv3x3s2_relu<256, 512, 56, 56, 64>
            <<<dim3(NTX * NTY, 8, BATCH), 128>>>(h3, w4, h4);
    }
    {   // L5: 512 -> 512, 28 -> 14  (NCO=32 -> 512 CTAs for parallelism)
        constexpr int NTX = (14 + 15) / 16, NTY = (14 + 3) / 4;
        conv3x3s2_relu<512, 512, 28, 28, 32>
            <<<dim3(NTX * NTY, 16, BATCH), 128>>>(h4, w5, h5);
    }

    yolo_head_kernel<<<dim3(BATCH, HEAD_OUT), 224>>>(h5, wh, pred);
    yolo_decode_kernel<<<BATCH, 224>>>(pred, boxes, cls, out);
    yolo_nms_kernel<<<dim3(NUM_CLS, BATCH), 224>>>(boxes, cls, out);
}

// round 11
// speedup vs baseline: 1.6961x; 1.4578x over previous
#include <cuda_runtime.h>
#include <math.h>
#include <stdint.h>

// ---------------------------------------------------------------------------
// Problem constants
// ---------------------------------------------------------------------------
#define BATCH      8
#define STRIDE_F   32.0f
#define N_CELLS    196         // 14*14
#define WS_GRID    14
#define NUM_CLS    20
#define HEAD_OUT   25          // 1 + 20 + 4
#define CONF_TH    0.01f
#define NMS_TH     0.5f

// ---------------------------------------------------------------------------
// Scratch (static __device__ arrays: allocation-free, capture-safe).
// Ping-pong aliasing, safe under sequential default-stream execution.
// ---------------------------------------------------------------------------
__device__ float g_bufA[8L * 64 * 224 * 224];    // 102.8 MB
__device__ float g_bufB[8L * 128 * 112 * 112];   //  51.4 MB
__device__ float g_pred [8 * HEAD_OUT * N_CELLS];
__device__ float g_boxes[8 * N_CELLS * 4];
__device__ float g_cls  [8 * N_CELLS * NUM_CLS];

// Pre-transposed weights: [co_blk][ci_chunk][cc*9+k][WPAD], per layer.
// Sizes (floats):
//  L1: 1*1*27*68      = 1836
//  L2: 2*16*36*68     = 78336
//  L3: 4*32*36*68     = 313344
//  L4: 8*64*36*68     = 1253376
//  L5: 16*128*36*36   = 2654208
#define WT_OFF1 0
#define WT_OFF2 (WT_OFF1 + 1836)
#define WT_OFF3 (WT_OFF2 + 78336)
#define WT_OFF4 (WT_OFF3 + 313344)
#define WT_OFF5 (WT_OFF4 + 1253376)
#define WT_TOTAL (WT_OFF5 + 2654208)
__device__ float g_wT[WT_TOTAL];                 // ~17.2 MB

// ---------------------------------------------------------------------------
// cp.async helpers (zero-fill via src-size operand)
// ---------------------------------------------------------------------------
__device__ __forceinline__ void cpa16(uint32_t dst, const void* src, bool p)
{
    int sz = p ? 16 : 0;
    asm volatile("cp.async.cg.shared.global [%0], [%1], 16, %2;"
                 :: "r"(dst), "l"(src), "r"(sz));
}
__device__ __forceinline__ void cpa4(uint32_t dst, const void* src, bool p)
{
    int sz = p ? 4 : 0;
    asm volatile("cp.async.ca.shared.global [%0], [%1], 4, %2;"
                 :: "r"(dst), "l"(src), "r"(sz));
}
__device__ __forceinline__ void cpa_commit()
{
    asm volatile("cp.async.commit_group;" ::: "memory");
}
__device__ __forceinline__ void cpa_wait0()
{
    asm volatile("cp.async.wait_group 0;" ::: "memory");
}

// ---------------------------------------------------------------------------
// Weight pre-transpose: w[co][ci][3][3] -> wT[blk][chunk][cc*9+k][WPAD]
// (pad columns co>=NCO are zero). Runs once per kernel_launch, ~microseconds.
// ---------------------------------------------------------------------------
template<int CIN, int COUT, int NCO>
__global__ void prep_weights(const float* __restrict__ w,
                             float* __restrict__ wT)
{
    constexpr int CHUNK = (CIN % 4 == 0) ? 4 : CIN;
    constexpr int WPAD  = NCO + 4 - (NCO == 32 ? 0 : 0);  // NCO+4
    constexpr int R     = CHUNK * 9;
    constexpr int NCH   = CIN / CHUNK;
    constexpr int NBLK  = COUT / NCO;
    const int total = NBLK * NCH * R * WPAD;
    for (int idx = blockIdx.x * blockDim.x + threadIdx.x; idx < total;
         idx += gridDim.x * blockDim.x) {
        const int co = idx % WPAD;
        int t  = idx / WPAD;
        const int r  = t % R;
        t /= R;
        const int ch  = t % NCH;
        const int blk = t / NCH;
        float v = 0.0f;
        if (co < NCO)
            v = w[(size_t)(blk * NCO + co) * CIN * 9 + ch * R + r];
        wT[idx] = v;
    }
}
// L5 uses WPAD = NCO+4 = 36 as well (NCO=32) — consistent with above.

// ---------------------------------------------------------------------------
// 3x3 stride-2 conv + ReLU, SAME padding (JAX: pad_lo=0, pad_hi=1).
//
// v7: cp.async double-buffered pipeline.
//  - Tile: NCO co x (4 rows x 16 cols); 128 threads; thread = NCO/8 co x 4 r.
//  - CHUNK=4 input channels per stage (3 for L1); 2-stage smem ping-pong.
//  - Input tile rows padded to 36 floats; loaded with 8x cp.async.16 +
//    1x cp.async.4 per row, zero-fill for OOB (WIN multiple of 4 -> 16B
//    chunks are fully in or fully out).
//  - Weights copied contiguously from the pre-transposed global layout
//    (16B cp.async, no transpose in-kernel).
//  - One __syncthreads per chunk; prefetch of chunk c+1 overlaps compute c.
//  - Compute identical FMA order to v6 -> bit-identical results.
// ---------------------------------------------------------------------------
template<int CIN, int COUT, int HIN, int WIN, int NCO>
__global__ __launch_bounds__(128, (NCO == 64 ? 6 : 8))
void conv3x3s2_relu(const float* __restrict__ in,
                    const float* __restrict__ wT,
                    float* __restrict__ out)
{
    constexpr int HOUT  = HIN / 2;
    constexpr int WOUT  = WIN / 2;
    constexpr int CHUNK = (CIN % 4 == 0) ? 4 : CIN;   // 4, or 3 for layer 1
    constexpr int NCH   = CIN / CHUNK;
    constexpr int NTX   = (WOUT + 15) / 16;
    constexpr int COT   = NCO / 8;                    // co per thread (8 or 4)
    constexpr int WPAD  = NCO + 4;
    constexpr int R     = CHUNK * 9;
    constexpr int IROW  = 36;                         // padded input row (floats)
    constexpr int ITEMS = CHUNK * 9 * 9;              // rows * 9 cp ops
    constexpr int WB    = R * WPAD / 4;               // weight float4 count

    const int bx  = blockIdx.x % NTX;
    const int by  = blockIdx.x / NTX;
    const int ox0 = bx * 16;
    const int oy0 = by * 4;
    const int b   = blockIdx.z;

    __shared__ __align__(16) float s_in[2][CHUNK * 9 * IROW];
    __shared__ __align__(16) float s_w [2][R * WPAD];

    const int tid = threadIdx.x;   // 0..127
    const int tc  = tid >> 4;      // 0..7
    const int tp  = tid & 15;      // 0..15 -> output column within tile

    float acc[COT][4] = {};        // [co][row]

    const float* in_b   = in + (size_t)b * CIN * HIN * WIN;
    const float* wT_blk = wT + (size_t)blockIdx.y * NCH * R * WPAD;

    // ---- loader (issued async; commit by caller) ----
    auto load_stage = [&](int ch, int buf) {
        // input tile: CHUNK channels x 9 rows x 33 cols (rows padded to 36)
        const int ci0 = ch * CHUNK;
#pragma unroll
        for (int i = 0; i < (ITEMS + 127) / 128; i++) {
            const int idx = tid + i * 128;
            if ((ITEMS % 128 == 0) || (idx < ITEMS)) {
                const int c   = idx % 9;
                const int row = idx / 9;        // cc*9 + ly
                const int cc  = row / 9;
                const int ly  = row - cc * 9;
                const int iy  = 2 * oy0 + ly;   // pad_lo = 0
                const float* src = in_b + ((size_t)(ci0 + cc) * HIN + iy) * WIN
                                        + 2 * ox0;
                const uint32_t dst = (uint32_t)__cvta_generic_to_shared(
                    &s_in[buf][row * IROW]);
                const bool rowok = (iy < HIN);
                if (c < 8) {
                    cpa16(dst + c * 16, src + c * 4,
                          rowok && (2 * ox0 + c * 4 < WIN));
                } else {
                    cpa4(dst + 128, src + 32, rowok && (2 * ox0 + 32 < WIN));
                }
            }
        }
        // weights: contiguous copy from pre-transposed layout
        const float* wsrc = wT_blk + (size_t)ch * R * WPAD;
        const uint32_t wdst = (uint32_t)__cvta_generic_to_shared(&s_w[buf][0]);
#pragma unroll
        for (int i = 0; i < (WB + 127) / 128; i++) {
            const int idx = tid + i * 128;
            if ((WB % 128 == 0) || (idx < WB))
                cpa16(wdst + idx * 16, wsrc + idx * 4, true);
        }
    };

    load_stage(0, 0);
    cpa_commit();

    for (int ch = 0; ch < NCH; ch++) {
        cpa_wait0();
        __syncthreads();
        if (ch + 1 < NCH) {
            load_stage(ch + 1, (ch + 1) & 1);
            cpa_commit();
        }

        // ---- compute from buffer ch&1 ----
        const float* pi = &s_in[ch & 1][0] + 2 * tp;
        const float* pw = &s_w [ch & 1][0] + tc * COT;

#pragma unroll 1
        for (int cc = 0; cc < CHUNK; cc++) {
#pragma unroll
            for (int ky = 0; ky < 3; ky++) {
#pragma unroll
                for (int kx = 0; kx < 3; kx++) {
                    const int kp = ky * 3 + kx;
                    const float4 wa = *reinterpret_cast<const float4*>(pw + kp * WPAD);
                    float4 wb;
                    if constexpr (COT == 8)
                        wb = *reinterpret_cast<const float4*>(pw + kp * WPAD + 4);
#pragma unroll
                    for (int r = 0; r < 4; r++) {
                        const int ly = 2 * r + ky;
                        const float iv = pi[ly * IROW + kx];
                        acc[0][r] = fmaf(wa.x, iv, acc[0][r]);
                        acc[1][r] = fmaf(wa.y, iv, acc[1][r]);
                        acc[2][r] = fmaf(wa.z, iv, acc[2][r]);
                        acc[3][r] = fmaf(wa.w, iv, acc[3][r]);
                        if constexpr (COT == 8) {
                            acc[4][r] = fmaf(wb.x, iv, acc[4][r]);
                            acc[5][r] = fmaf(wb.y, iv, acc[5][r]);
                            acc[6][r] = fmaf(wb.z, iv, acc[6][r]);
                            acc[7][r] = fmaf(wb.w, iv, acc[7][r]);
                        }
                    }
                }
            }
            pi += 9 * IROW;    // next input channel
            pw += 9 * WPAD;    // next weight channel
        }
    }

    // ---- epilogue: ReLU + store ----
    const int co0 = blockIdx.y * NCO;
    float* out_b = out + (size_t)b * COUT * HOUT * WOUT;
    const int ox = ox0 + tp;
    if (ox < WOUT) {
#pragma unroll
        for (int j = 0; j < COT; j++) {
            const int co = co0 + tc * COT + j;
#pragma unroll
            for (int r = 0; r < 4; r++) {
                const int oy = oy0 + r;
                if (oy < HOUT)
                    out_b[((size_t)co * HOUT + oy) * WOUT + ox] = fmaxf(acc[j][r], 0.0f);
            }
        }
    }
}

// ---------------------------------------------------------------------------
// 1x1 head conv: pred[b][o][p] = sum_ci h5[b][ci][p] * w[o][ci]
// ---------------------------------------------------------------------------
__global__ void yolo_head_kernel(const float* __restrict__ h5,
                                 const float* __restrict__ w,
                                 float* __restrict__ pred)
{
    const int b = blockIdx.x;
    const int o = blockIdx.y;
    const int p = threadIdx.x;
    if (p >= N_CELLS) return;
    const float* hb = h5 + (size_t)b * 512 * N_CELLS;
    const float* wo = w + o * 512;
    float s = 0.0f;
#pragma unroll 8
    for (int ci = 0; ci < 512; ci++)
        s = fmaf(hb[ci * N_CELLS + p], wo[ci], s);
    pred[(b * HEAD_OUT + o) * N_CELLS + p] = s;
}

// ---------------------------------------------------------------------------
// Decode: sigmoid conf, softmax*conf class scores, box decode + clip.
// ---------------------------------------------------------------------------
__global__ void yolo_decode_kernel(const float* __restrict__ pred,
                                   float* __restrict__ boxes,
                                   float* __restrict__ cls,
                                   float* __restrict__ out)
{
    const int b = blockIdx.x;
    const int p = threadIdx.x;
    if (p >= N_CELLS) return;
    const float* pb = pred + (size_t)b * HEAD_OUT * N_CELLS;

    float conf = 1.0f / (1.0f + expf(-pb[p]));

    float v[NUM_CLS];
    float m = -1e30f;
#pragma unroll
    for (int c = 0; c < NUM_CLS; c++) {
        v[c] = pb[(1 + c) * N_CELLS + p];
        m = fmaxf(m, v[c]);
    }
    float s = 0.0f;
#pragma unroll
    for (int c = 0; c < NUM_CLS; c++) { v[c] = expf(v[c] - m); s += v[c]; }
    float inv = conf / s;

    float tx = pb[21 * N_CELLS + p];
    float ty = pb[22 * N_CELLS + p];
    float tw = pb[23 * N_CELLS + p];
    float th = pb[24 * N_CELLS + p];

    float gx = (float)(p % WS_GRID);
    float gy = (float)(p / WS_GRID);
    float cx = (1.0f / (1.0f + expf(-tx)) + gx) * STRIDE_F;
    float cy = (1.0f / (1.0f + expf(-ty)) + gy) * STRIDE_F;
    float bw = expf(tw) * STRIDE_F;
    float bh = expf(th) * STRIDE_F;

    float x1 = (cx - bw * 0.5f) / 448.0f;
    float y1 = (cy - bh * 0.5f) / 448.0f;
    float x2 = (cx + bw * 0.5f) / 448.0f;
    float y2 = (cy + bh * 0.5f) / 448.0f;
    x1 = fminf(fmaxf(x1, 0.0f), 1.0f);
    y1 = fminf(fmaxf(y1, 0.0f), 1.0f);
    x2 = fminf(fmaxf(x2, 0.0f), 1.0f);
    y2 = fminf(fmaxf(y2, 0.0f), 1.0f);

    const int row = b * N_CELLS + p;
    boxes[row * 4 + 0] = x1;
    boxes[row * 4 + 1] = y1;
    boxes[row * 4 + 2] = x2;
    boxes[row * 4 + 3] = y2;
    out[row * 24 + 0] = x1;
    out[row * 24 + 1] = y1;
    out[row * 24 + 2] = x2;
    out[row * 24 + 3] = y2;
#pragma unroll
    for (int c = 0; c < NUM_CLS; c++)
        cls[row * NUM_CLS + c] = v[c] * inv;
}

// ---------------------------------------------------------------------------
// Per-(batch, class) greedy NMS. One block per problem.
// Stable descending rank (== stable argsort of -scores), then 196
// barrier-stepped suppression iterations (only kept boxes suppress).
// ---------------------------------------------------------------------------
__global__ void yolo_nms_kernel(const float* __restrict__ boxes,
                                const float* __restrict__ cls,
                                float* __restrict__ out)
{
    const int c = blockIdx.x;   // class
    const int b = blockIdx.y;   // batch
    const int t = threadIdx.x;

    __shared__ float ss[N_CELLS];
    __shared__ float sx1[N_CELLS], sy1[N_CELLS], sx2[N_CELLS], sy2[N_CELLS];
    __shared__ float sa[N_CELLS];
    __shared__ int   sorder[N_CELLS];
    __shared__ int   skeep[N_CELLS];

    if (t < N_CELLS) {
        const int row = b * N_CELLS + t;
        ss[t] = cls[row * NUM_CLS + c];
        float x1 = boxes[row * 4 + 0];
        float y1 = boxes[row * 4 + 1];
        float x2 = boxes[row * 4 + 2];
        float y2 = boxes[row * 4 + 3];
        sx1[t] = x1; sy1[t] = y1; sx2[t] = x2; sy2[t] = y2;
        sa[t] = fmaxf(x2 - x1, 0.0f) * fmaxf(y2 - y1, 0.0f);
    }
    __syncthreads();

    if (t < N_CELLS) {
        float sp = ss[t];
        int r = 0;
        for (int q = 0; q < N_CELLS; q++) {
            float sq = ss[q];
            r += (sq > sp) || (sq == sp && q < t);
        }
        sorder[r] = t;
        skeep[r]  = (sp > CONF_TH) ? 1 : 0;
    }
    __syncthreads();

    int pj = 0;
    float bx1 = 0.f, by1 = 0.f, bx2 = 0.f, by2 = 0.f, ba = 0.f;
    if (t < N_CELLS) {
        pj  = sorder[t];
        bx1 = sx1[pj]; by1 = sy1[pj]; bx2 = sx2[pj]; by2 = sy2[pj]; ba = sa[pj];
    }

    for (int i = 0; i < N_CELLS - 1; i++) {
        if (skeep[i]) {
            int pi = sorder[i];
            float ax1 = sx1[pi], ay1 = sy1[pi];
            float ax2 = sx2[pi], ay2 = sy2[pi];
            float aa  = sa[pi];
            if (t < N_CELLS && t > i && skeep[t]) {
                float ix1 = fmaxf(ax1, bx1), iy1 = fmaxf(ay1, by1);
                float ix2 = fminf(ax2, bx2), iy2 = fminf(ay2, by2);
                float inter = fmaxf(ix2 - ix1, 0.0f) * fmaxf(iy2 - iy1, 0.0f);
                float iou = inter / (aa + ba - inter + 1e-14f);
                if (iou > NMS_TH) skeep[t] = 0;
            }
        }
        __syncthreads();
    }

    if (t < N_CELLS) {
        const int row = b * N_CELLS + pj;
        out[row * 24 + 4 + c] = ss[pj] * (skeep[t] ? 1.0f : 0.0f);
    }
}

// ---------------------------------------------------------------------------
// Launch
// ---------------------------------------------------------------------------
extern "C" void kernel_launch(void* const* d_in, const int* in_sizes, int n_in,
                              void* d_out, int out_size)
{
    const float* x  = (const float*)d_in[0];
    const float* w1 = (const float*)d_in[1];
    const float* w2 = (const float*)d_in[2];
    const float* w3 = (const float*)d_in[3];
    const float* w4 = (const float*)d_in[4];
    const float* w5 = (const float*)d_in[5];
    const float* wh = (const float*)d_in[6];
    float* out = (float*)d_out;

    float *bufA, *bufB, *pred, *boxes, *cls, *wT;
    cudaGetSymbolAddress((void**)&bufA, g_bufA);
    cudaGetSymbolAddress((void**)&bufB, g_bufB);
    cudaGetSymbolAddress((void**)&pred, g_pred);
    cudaGetSymbolAddress((void**)&boxes, g_boxes);
    cudaGetSymbolAddress((void**)&cls, g_cls);
    cudaGetSymbolAddress((void**)&wT, g_wT);

    float* h1 = bufA;
    float* h2 = bufB;
    float* h3 = bufA;
    float* h4 = bufB;
    float* h5 = bufA;

    // ---- weight pre-transpose (few microseconds total) ----
    prep_weights<3,   64,  64><<<16,  256>>>(w1, wT + WT_OFF1);
    prep_weights<64,  128, 64><<<64,  256>>>(w2, wT + WT_OFF2);
    prep_weights<128, 256, 64><<<256, 256>>>(w3, wT + WT_OFF3);
    prep_weights<256, 512, 64><<<512, 256>>>(w4, wT + WT_OFF4);
    prep_weights<512, 512, 32><<<512, 256>>>(w5, wT + WT_OFF5);

    {   // L1: 3 -> 64, 448 -> 224
        constexpr int NTX = (224 + 15) / 16, NTY = (224 + 3) / 4;
        conv3x3s2_relu<3, 64, 448, 448, 64>
            <<<dim3(NTX * NTY, 1, BATCH), 128>>>(x, wT + WT_OFF1, h1);
    }
    {   // L2: 64 -> 128, 224 -> 112
        constexpr int NTX = (112 + 15) / 16, NTY = (112 + 3) / 4;
        conv3x3s2_relu<64, 128, 224, 224, 64>
            <<<dim3(NTX * NTY, 2, BATCH), 128>>>(h1, wT + WT_OFF2, h2);
    }
    {   // L3: 128 -> 256, 112 -> 56
        constexpr int NTX = (56 + 15) / 16, NTY = (56 + 3) / 4;
        conv3x3s2_relu<128, 256, 112, 112, 64>
            <<<dim3(NTX * NTY, 4, BATCH), 128>>>(h2, wT + WT_OFF3, h3);
    }
    {   // L4: 256 -> 512, 56 -> 28
        constexpr int NTX = (28 + 15) / 16, NTY = (28 + 3) / 4;
        conv3x3s2_relu<256, 512, 56, 56, 64>
            <<<dim3(NTX * NTY, 8, BATCH), 128>>>(h3, wT + WT_OFF4, h4);
    }
    {   // L5: 512 -> 512, 28 -> 14  (NCO=32 -> 512 CTAs for parallelism)
        constexpr int NTX = (14 + 15) / 16, NTY = (14 + 3) / 4;
        conv3x3s2_relu<512, 512, 28, 28, 32>
            <<<dim3(NTX * NTY, 16, BATCH), 128>>>(h4, wT + WT_OFF5, h5);
    }

    yolo_head_kernel<<<dim3(BATCH, HEAD_OUT), 224>>>(h5, wh, pred);
    yolo_decode_kernel<<<BATCH, 224>>>(pred, boxes, cls, out);
    yolo_nms_kernel<<<dim3(NUM_CLS, BATCH), 224>>>(boxes, cls, out);
}

// round 13
// speedup vs baseline: 1.8486x; 1.0899x over previous
#include <cuda_runtime.h>
#include <math.h>
#include <stdint.h>

// ---------------------------------------------------------------------------
// Problem constants
// ---------------------------------------------------------------------------
#define BATCH      8
#define STRIDE_F   32.0f
#define N_CELLS    196         // 14*14
#define WS_GRID    14
#define NUM_CLS    20
#define HEAD_OUT   25          // 1 + 20 + 4
#define CONF_TH    0.01f
#define NMS_TH     0.5f

// ---------------------------------------------------------------------------
// Scratch (static __device__ arrays: allocation-free, capture-safe).
// ---------------------------------------------------------------------------
__device__ float g_bufA[8L * 64 * 224 * 224];    // 102.8 MB
__device__ float g_bufB[8L * 128 * 112 * 112];   //  51.4 MB
__device__ float g_pred [8 * HEAD_OUT * N_CELLS];
__device__ float g_boxes[8 * N_CELLS * 4];
__device__ float g_cls  [8 * N_CELLS * NUM_CLS];

// Pre-transposed weights: [co_blk][ci_chunk][cc*9+k][WPAD], per layer.
#define WT_OFF1 0
#define WT_OFF2 (WT_OFF1 + 1836)
#define WT_OFF3 (WT_OFF2 + 78336)
#define WT_OFF4 (WT_OFF3 + 313344)
#define WT_OFF5 (WT_OFF4 + 1253376)
#define WT_TOTAL (WT_OFF5 + 2654208)
__device__ float g_wT[WT_TOTAL];                 // ~17.2 MB

// ---------------------------------------------------------------------------
// cp.async helpers (zero-fill via src-size operand)
// ---------------------------------------------------------------------------
__device__ __forceinline__ void cpa16(uint32_t dst, const void* src, bool p)
{
    int sz = p ? 16 : 0;
    asm volatile("cp.async.cg.shared.global [%0], [%1], 16, %2;"
                 :: "r"(dst), "l"(src), "r"(sz));
}
__device__ __forceinline__ void cpa4(uint32_t dst, const void* src, bool p)
{
    int sz = p ? 4 : 0;
    asm volatile("cp.async.ca.shared.global [%0], [%1], 4, %2;"
                 :: "r"(dst), "l"(src), "r"(sz));
}
__device__ __forceinline__ void cpa_commit()
{
    asm volatile("cp.async.commit_group;" ::: "memory");
}
__device__ __forceinline__ void cpa_wait0()
{
    asm volatile("cp.async.wait_group 0;" ::: "memory");
}

// ---------------------------------------------------------------------------
// Packed fp32x2 helpers (sm_103a FFMA2 — PTX-only; per-lane .rn == fmaf,
// so packed results are bit-identical to the scalar accumulation).
// ---------------------------------------------------------------------------
__device__ __forceinline__ unsigned long long fma2(unsigned long long a,
                                                   unsigned long long b,
                                                   unsigned long long c)
{
    unsigned long long d;
    asm("fma.rn.f32x2 %0, %1, %2, %3;" : "=l"(d) : "l"(a), "l"(b), "l"(c));
    return d;
}
__device__ __forceinline__ unsigned long long bcast2(float v)
{
    unsigned long long d;
    asm("mov.b64 %0, {%1, %1};" : "=l"(d) : "f"(v));
    return d;
}
__device__ __forceinline__ void unpack2(unsigned long long p, float& lo, float& hi)
{
    asm("mov.b64 {%0, %1}, %2;" : "=f"(lo), "=f"(hi) : "l"(p));
}

// ---------------------------------------------------------------------------
// Weight pre-transpose: w[co][ci][3][3] -> wT[blk][chunk][cc*9+k][WPAD]
// ---------------------------------------------------------------------------
template<int CIN, int COUT, int NCO>
__global__ void prep_weights(const float* __restrict__ w,
                             float* __restrict__ wT)
{
    constexpr int CHUNK = (CIN % 4 == 0) ? 4 : CIN;
    constexpr int WPAD  = NCO + 4;
    constexpr int R     = CHUNK * 9;
    constexpr int NCH   = CIN / CHUNK;
    constexpr int NBLK  = COUT / NCO;
    const int total = NBLK * NCH * R * WPAD;
    for (int idx = blockIdx.x * blockDim.x + threadIdx.x; idx < total;
         idx += gridDim.x * blockDim.x) {
        const int co = idx % WPAD;
        int t  = idx / WPAD;
        const int r  = t % R;
        t /= R;
        const int ch  = t % NCH;
        const int blk = t / NCH;
        float v = 0.0f;
        if (co < NCO)
            v = w[(size_t)(blk * NCO + co) * CIN * 9 + ch * R + r];
        wT[idx] = v;
    }
}

// ---------------------------------------------------------------------------
// 3x3 stride-2 conv + ReLU, SAME padding (JAX: pad_lo=0, pad_hi=1).
//
// v8 = v7 cp.async double-buffered pipeline + FFMA2 co-pair compute.
//  - Tile: NCO co x (4 rows x 16 cols); 128 threads.
//  - Accumulators packed over (co, co+1) pairs: COT/2 x 4 x 64-bit (32 regs).
//  - Weight pairs come straight out of LDS.128 (ulonglong2) — no pack MOVs;
//    one mov.b64 broadcast per input value (hoisted per k-position).
//  - Same accumulation order as scalar -> bit-identical output.
//  - launch_bounds 5 CTAs for NCO=64 (reg headroom; R7 failed at a hard cap).
// ---------------------------------------------------------------------------
template<int CIN, int COUT, int HIN, int WIN, int NCO>
__global__ __launch_bounds__(128, (NCO == 64 ? 5 : 8))
void conv3x3s2_relu(const float* __restrict__ in,
                    const float* __restrict__ wT,
                    float* __restrict__ out)
{
    constexpr int HOUT  = HIN / 2;
    constexpr int WOUT  = WIN / 2;
    constexpr int CHUNK = (CIN % 4 == 0) ? 4 : CIN;   // 4, or 3 for layer 1
    constexpr int NCH   = CIN / CHUNK;
    constexpr int NTX   = (WOUT + 15) / 16;
    constexpr int COT   = NCO / 8;                    // co per thread (8 or 4)
    constexpr int CP    = COT / 2;                    // co pairs (4 or 2)
    constexpr int WPAD  = NCO + 4;
    constexpr int R     = CHUNK * 9;
    constexpr int IROW  = 36;                         // padded input row
    constexpr int ITEMS = CHUNK * 9 * 9;              // rows * 9 cp ops
    constexpr int WB    = R * WPAD / 4;               // weight float4 count

    const int bx  = blockIdx.x % NTX;
    const int by  = blockIdx.x / NTX;
    const int ox0 = bx * 16;
    const int oy0 = by * 4;
    const int b   = blockIdx.z;

    __shared__ __align__(16) float s_in[2][CHUNK * 9 * IROW];
    __shared__ __align__(16) float s_w [2][R * WPAD];

    const int tid = threadIdx.x;   // 0..127
    const int tc  = tid >> 4;      // 0..7
    const int tp  = tid & 15;      // 0..15 -> output column within tile

    unsigned long long acc[CP][4] = {};   // [co-pair][row]

    const float* in_b   = in + (size_t)b * CIN * HIN * WIN;
    const float* wT_blk = wT + (size_t)blockIdx.y * NCH * R * WPAD;

    auto load_stage = [&](int ch, int buf) {
        const int ci0 = ch * CHUNK;
#pragma unroll
        for (int i = 0; i < (ITEMS + 127) / 128; i++) {
            const int idx = tid + i * 128;
            if ((ITEMS % 128 == 0) || (idx < ITEMS)) {
                const int c   = idx % 9;
                const int row = idx / 9;        // cc*9 + ly
                const int cc  = row / 9;
                const int ly  = row - cc * 9;
                const int iy  = 2 * oy0 + ly;   // pad_lo = 0
                const float* src = in_b + ((size_t)(ci0 + cc) * HIN + iy) * WIN
                                        + 2 * ox0;
                const uint32_t dst = (uint32_t)__cvta_generic_to_shared(
                    &s_in[buf][row * IROW]);
                const bool rowok = (iy < HIN);
                if (c < 8) {
                    cpa16(dst + c * 16, src + c * 4,
                          rowok && (2 * ox0 + c * 4 < WIN));
                } else {
                    cpa4(dst + 128, src + 32, rowok && (2 * ox0 + 32 < WIN));
                }
            }
        }
        const float* wsrc = wT_blk + (size_t)ch * R * WPAD;
        const uint32_t wdst = (uint32_t)__cvta_generic_to_shared(&s_w[buf][0]);
#pragma unroll
        for (int i = 0; i < (WB + 127) / 128; i++) {
            const int idx = tid + i * 128;
            if ((WB % 128 == 0) || (idx < WB))
                cpa16(wdst + idx * 16, wsrc + idx * 4, true);
        }
    };

    load_stage(0, 0);
    cpa_commit();

    for (int ch = 0; ch < NCH; ch++) {
        cpa_wait0();
        __syncthreads();
        if (ch + 1 < NCH) {
            load_stage(ch + 1, (ch + 1) & 1);
            cpa_commit();
        }

        // ---- compute from buffer ch&1: packed co-pair FFMA2 ----
        const float* pi = &s_in[ch & 1][0] + 2 * tp;
        const float* pw = &s_w [ch & 1][0] + tc * COT;

#pragma unroll 1
        for (int cc = 0; cc < CHUNK; cc++) {
#pragma unroll
            for (int ky = 0; ky < 3; ky++) {
#pragma unroll
                for (int kx = 0; kx < 3; kx++) {
                    const int kp = ky * 3 + kx;
                    // LDS.128 delivers two packed (co,co+1) weight pairs
                    const ulonglong2 wA =
                        *reinterpret_cast<const ulonglong2*>(pw + kp * WPAD);
                    ulonglong2 wB;
                    if constexpr (CP == 4)
                        wB = *reinterpret_cast<const ulonglong2*>(pw + kp * WPAD + 4);
                    // hoisted input broadcasts (4 LDS.32 + 4 mov.b64)
                    unsigned long long iv2[4];
#pragma unroll
                    for (int r = 0; r < 4; r++)
                        iv2[r] = bcast2(pi[(2 * r + ky) * IROW + kx]);
#pragma unroll
                    for (int r = 0; r < 4; r++) {
                        acc[0][r] = fma2(wA.x, iv2[r], acc[0][r]);
                        acc[1][r] = fma2(wA.y, iv2[r], acc[1][r]);
                        if constexpr (CP == 4) {
                            acc[2][r] = fma2(wB.x, iv2[r], acc[2][r]);
                            acc[3][r] = fma2(wB.y, iv2[r], acc[3][r]);
                        }
                    }
                }
            }
            pi += 9 * IROW;    // next input channel
            pw += 9 * WPAD;    // next weight channel
        }
    }

    // ---- epilogue: unpack, ReLU, store ----
    const int co0 = blockIdx.y * NCO;
    float* out_b = out + (size_t)b * COUT * HOUT * WOUT;
    const int ox = ox0 + tp;
    if (ox < WOUT) {
#pragma unroll
        for (int j2 = 0; j2 < CP; j2++) {
            const int co = co0 + tc * COT + 2 * j2;
#pragma unroll
            for (int r = 0; r < 4; r++) {
                const int oy = oy0 + r;
                if (oy < HOUT) {
                    float lo, hi;
                    unpack2(acc[j2][r], lo, hi);
                    out_b[((size_t)co * HOUT + oy) * WOUT + ox]       = fmaxf(lo, 0.0f);
                    out_b[((size_t)(co + 1) * HOUT + oy) * WOUT + ox] = fmaxf(hi, 0.0f);
                }
            }
        }
    }
}

// ---------------------------------------------------------------------------
// 1x1 head conv: pred[b][o][p] = sum_ci h5[b][ci][p] * w[o][ci]
// ---------------------------------------------------------------------------
__global__ void yolo_head_kernel(const float* __restrict__ h5,
                                 const float* __restrict__ w,
                                 float* __restrict__ pred)
{
    const int b = blockIdx.x;
    const int o = blockIdx.y;
    const int p = threadIdx.x;
    if (p >= N_CELLS) return;
    const float* hb = h5 + (size_t)b * 512 * N_CELLS;
    const float* wo = w + o * 512;
    float s = 0.0f;
#pragma unroll 8
    for (int ci = 0; ci < 512; ci++)
        s = fmaf(hb[ci * N_CELLS + p], wo[ci], s);
    pred[(b * HEAD_OUT + o) * N_CELLS + p] = s;
}

// ---------------------------------------------------------------------------
// Decode: sigmoid conf, softmax*conf class scores, box decode + clip.
// ---------------------------------------------------------------------------
__global__ void yolo_decode_kernel(const float* __restrict__ pred,
                                   float* __restrict__ boxes,
                                   float* __restrict__ cls,
                                   float* __restrict__ out)
{
    const int b = blockIdx.x;
    const int p = threadIdx.x;
    if (p >= N_CELLS) return;
    const float* pb = pred + (size_t)b * HEAD_OUT * N_CELLS;

    float conf = 1.0f / (1.0f + expf(-pb[p]));

    float v[NUM_CLS];
    float m = -1e30f;
#pragma unroll
    for (int c = 0; c < NUM_CLS; c++) {
        v[c] = pb[(1 + c) * N_CELLS + p];
        m = fmaxf(m, v[c]);
    }
    float s = 0.0f;
#pragma unroll
    for (int c = 0; c < NUM_CLS; c++) { v[c] = expf(v[c] - m); s += v[c]; }
    float inv = conf / s;

    float tx = pb[21 * N_CELLS + p];
    float ty = pb[22 * N_CELLS + p];
    float tw = pb[23 * N_CELLS + p];
    float th = pb[24 * N_CELLS + p];

    float gx = (float)(p % WS_GRID);
    float gy = (float)(p / WS_GRID);
    float cx = (1.0f / (1.0f + expf(-tx)) + gx) * STRIDE_F;
    float cy = (1.0f / (1.0f + expf(-ty)) + gy) * STRIDE_F;
    float bw = expf(tw) * STRIDE_F;
    float bh = expf(th) * STRIDE_F;

    float x1 = (cx - bw * 0.5f) / 448.0f;
    float y1 = (cy - bh * 0.5f) / 448.0f;
    float x2 = (cx + bw * 0.5f) / 448.0f;
    float y2 = (cy + bh * 0.5f) / 448.0f;
    x1 = fminf(fmaxf(x1, 0.0f), 1.0f);
    y1 = fminf(fmaxf(y1, 0.0f), 1.0f);
    x2 = fminf(fmaxf(x2, 0.0f), 1.0f);
    y2 = fminf(fmaxf(y2, 0.0f), 1.0f);

    const int row = b * N_CELLS + p;
    boxes[row * 4 + 0] = x1;
    boxes[row * 4 + 1] = y1;
    boxes[row * 4 + 2] = x2;
    boxes[row * 4 + 3] = y2;
    out[row * 24 + 0] = x1;
    out[row * 24 + 1] = y1;
    out[row * 24 + 2] = x2;
    out[row * 24 + 3] = y2;
#pragma unroll
    for (int c = 0; c < NUM_CLS; c++)
        cls[row * NUM_CLS + c] = v[c] * inv;
}

// ---------------------------------------------------------------------------
// Per-(batch, class) greedy NMS. One block per problem.
// ---------------------------------------------------------------------------
__global__ void yolo_nms_kernel(const float* __restrict__ boxes,
                                const float* __restrict__ cls,
                                float* __restrict__ out)
{
    const int c = blockIdx.x;   // class
    const int b = blockIdx.y;   // batch
    const int t = threadIdx.x;

    __shared__ float ss[N_CELLS];
    __shared__ float sx1[N_CELLS], sy1[N_CELLS], sx2[N_CELLS], sy2[N_CELLS];
    __shared__ float sa[N_CELLS];
    __shared__ int   sorder[N_CELLS];
    __shared__ int   skeep[N_CELLS];

    if (t < N_CELLS) {
        const int row = b * N_CELLS + t;
        ss[t] = cls[row * NUM_CLS + c];
        float x1 = boxes[row * 4 + 0];
        float y1 = boxes[row * 4 + 1];
        float x2 = boxes[row * 4 + 2];
        float y2 = boxes[row * 4 + 3];
        sx1[t] = x1; sy1[t] = y1; sx2[t] = x2; sy2[t] = y2;
        sa[t] = fmaxf(x2 - x1, 0.0f) * fmaxf(y2 - y1, 0.0f);
    }
    __syncthreads();

    if (t < N_CELLS) {   // stable descending rank (== stable argsort of -s)
        float sp = ss[t];
        int r = 0;
        for (int q = 0; q < N_CELLS; q++) {
            float sq = ss[q];
            r += (sq > sp) || (sq == sp && q < t);
        }
        sorder[r] = t;
        skeep[r]  = (sp > CONF_TH) ? 1 : 0;
    }
    __syncthreads();

    int pj = 0;
    float bx1 = 0.f, by1 = 0.f, bx2 = 0.f, by2 = 0.f, ba = 0.f;
    if (t < N_CELLS) {
        pj  = sorder[t];
        bx1 = sx1[pj]; by1 = sy1[pj]; bx2 = sx2[pj]; by2 = sy2[pj]; ba = sa[pj];
    }

    for (int i = 0; i < N_CELLS - 1; i++) {
        if (skeep[i]) {
            int pi = sorder[i];
            float ax1 = sx1[pi], ay1 = sy1[pi];
            float ax2 = sx2[pi], ay2 = sy2[pi];
            float aa  = sa[pi];
            if (t < N_CELLS && t > i && skeep[t]) {
                float ix1 = fmaxf(ax1, bx1), iy1 = fmaxf(ay1, by1);
                float ix2 = fminf(ax2, bx2), iy2 = fminf(ay2, by2);
                float inter = fmaxf(ix2 - ix1, 0.0f) * fmaxf(iy2 - iy1, 0.0f);
                float iou = inter / (aa + ba - inter + 1e-14f);
                if (iou > NMS_TH) skeep[t] = 0;
            }
        }
        __syncthreads();
    }

    if (t < N_CELLS) {
        const int row = b * N_CELLS + pj;
        out[row * 24 + 4 + c] = ss[pj] * (skeep[t] ? 1.0f : 0.0f);
    }
}

// ---------------------------------------------------------------------------
// Launch
// ---------------------------------------------------------------------------
extern "C" void kernel_launch(void* const* d_in, const int* in_sizes, int n_in,
                              void* d_out, int out_size)
{
    const float* x  = (const float*)d_in[0];
    const float* w1 = (const float*)d_in[1];
    const float* w2 = (const float*)d_in[2];
    const float* w3 = (const float*)d_in[3];
    const float* w4 = (const float*)d_in[4];
    const float* w5 = (const float*)d_in[5];
    const float* wh = (const float*)d_in[6];
    float* out = (float*)d_out;

    float *bufA, *bufB, *pred, *boxes, *cls, *wT;
    cudaGetSymbolAddress((void**)&bufA, g_bufA);
    cudaGetSymbolAddress((void**)&bufB, g_bufB);
    cudaGetSymbolAddress((void**)&pred, g_pred);
    cudaGetSymbolAddress((void**)&boxes, g_boxes);
    cudaGetSymbolAddress((void**)&cls, g_cls);
    cudaGetSymbolAddress((void**)&wT, g_wT);

    float* h1 = bufA;
    float* h2 = bufB;
    float* h3 = bufA;
    float* h4 = bufB;
    float* h5 = bufA;

    // ---- weight pre-transpose ----
    prep_weights<3,   64,  64><<<16,  256>>>(w1, wT + WT_OFF1);
    prep_weights<64,  128, 64><<<64,  256>>>(w2, wT + WT_OFF2);
    prep_weights<128, 256, 64><<<256, 256>>>(w3, wT + WT_OFF3);
    prep_weights<256, 512, 64><<<512, 256>>>(w4, wT + WT_OFF4);
    prep_weights<512, 512, 32><<<512, 256>>>(w5, wT + WT_OFF5);

    {   // L1: 3 -> 64, 448 -> 224
        constexpr int NTX = (224 + 15) / 16, NTY = (224 + 3) / 4;
        conv3x3s2_relu<3, 64, 448, 448, 64>
            <<<dim3(NTX * NTY, 1, BATCH), 128>>>(x, wT + WT_OFF1, h1);
    }
    {   // L2: 64 -> 128, 224 -> 112
        constexpr int NTX = (112 + 15) / 16, NTY = (112 + 3) / 4;
        conv3x3s2_relu<64, 128, 224, 224, 64>
            <<<dim3(NTX * NTY, 2, BATCH), 128>>>(h1, wT + WT_OFF2, h2);
    }
    {   // L3: 128 -> 256, 112 -> 56
        constexpr int NTX = (56 + 15) / 16, NTY = (56 + 3) / 4;
        conv3x3s2_relu<128, 256, 112, 112, 64>
            <<<dim3(NTX * NTY, 4, BATCH), 128>>>(h2, wT + WT_OFF3, h3);
    }
    {   // L4: 256 -> 512, 56 -> 28
        constexpr int NTX = (28 + 15) / 16, NTY = (28 + 3) / 4;
        conv3x3s2_relu<256, 512, 56, 56, 64>
            <<<dim3(NTX * NTY, 8, BATCH), 128>>>(h3, wT + WT_OFF4, h4);
    }
    {   // L5: 512 -> 512, 28 -> 14  (NCO=32 -> 512 CTAs for parallelism)
        constexpr int NTX = (14 + 15) / 16, NTY = (14 + 3) / 4;
        conv3x3s2_relu<512, 512, 28, 28, 32>
            <<<dim3(NTX * NTY, 16, BATCH), 128>>>(h4, wT + WT_OFF5, h5);
    }

    yolo_head_kernel<<<dim3(BATCH, HEAD_OUT), 224>>>(h5, wh, pred);
    yolo_decode_kernel<<<BATCH, 224>>>(pred, boxes, cls, out);
    yolo_nms_kernel<<<dim3(NUM_CLS, BATCH), 224>>>(boxes, cls, out);
}

// round 15
// speedup vs baseline: 1.8836x; 1.0190x over previous
#include <cuda_runtime.h>
#include <math.h>
#include <stdint.h>

// ---------------------------------------------------------------------------
// Problem constants
// ---------------------------------------------------------------------------
#define BATCH      8
#define STRIDE_F   32.0f
#define N_CELLS    196         // 14*14
#define WS_GRID    14
#define NUM_CLS    20
#define HEAD_OUT   25          // 1 + 20 + 4
#define CONF_TH    0.01f
#define NMS_TH     0.5f

// Per-layer input-channel chunk (shared by prep + conv — MUST match).
// __host__ __device__ so it is callable from __global__ templates without
// --expt-relaxed-constexpr (the R14 compile failure).
__host__ __device__ constexpr int chunk_of(int cin)
{
    return (cin >= 128 && cin % 8 == 0) ? 8 : ((cin % 4 == 0) ? 4 : cin);
}

// ---------------------------------------------------------------------------
// Scratch (static __device__ arrays: allocation-free, capture-safe).
// ---------------------------------------------------------------------------
__device__ float g_bufA[8L * 64 * 224 * 224];    // 102.8 MB
__device__ float g_bufB[8L * 128 * 112 * 112];   //  51.4 MB
__device__ float g_pred [8 * HEAD_OUT * N_CELLS];
__device__ float g_boxes[8 * N_CELLS * 4];
__device__ float g_cls  [8 * N_CELLS * NUM_CLS];

// Pre-transposed weights: [co_blk][ci_chunk][cc*9+k][WPAD], per layer.
// Total floats per layer = (COUT/NCO) * CIN*9 * WPAD  (chunking-invariant).
#define WT_OFF1 0
#define WT_OFF2 (WT_OFF1 + 1836)
#define WT_OFF3 (WT_OFF2 + 78336)
#define WT_OFF4 (WT_OFF3 + 313344)
#define WT_OFF5 (WT_OFF4 + 1253376)
#define WT_TOTAL (WT_OFF5 + 2654208)
__device__ float g_wT[WT_TOTAL];                 // ~17.2 MB

// ---------------------------------------------------------------------------
// cp.async helpers (zero-fill via src-size operand)
// ---------------------------------------------------------------------------
__device__ __forceinline__ void cpa16(uint32_t dst, const void* src, bool p)
{
    int sz = p ? 16 : 0;
    asm volatile("cp.async.cg.shared.global [%0], [%1], 16, %2;"
                 :: "r"(dst), "l"(src), "r"(sz));
}
__device__ __forceinline__ void cpa4(uint32_t dst, const void* src, bool p)
{
    int sz = p ? 4 : 0;
    asm volatile("cp.async.ca.shared.global [%0], [%1], 4, %2;"
                 :: "r"(dst), "l"(src), "r"(sz));
}
__device__ __forceinline__ void cpa_commit()
{
    asm volatile("cp.async.commit_group;" ::: "memory");
}
__device__ __forceinline__ void cpa_wait0()
{
    asm volatile("cp.async.wait_group 0;" ::: "memory");
}

// ---------------------------------------------------------------------------
// Packed fp32x2 helpers (sm_103a FFMA2 — PTX-only; per-lane .rn == fmaf,
// so packed results are bit-identical to the scalar accumulation).
// ---------------------------------------------------------------------------
__device__ __forceinline__ unsigned long long fma2(unsigned long long a,
                                                   unsigned long long b,
                                                   unsigned long long c)
{
    unsigned long long d;
    asm("fma.rn.f32x2 %0, %1, %2, %3;" : "=l"(d) : "l"(a), "l"(b), "l"(c));
    return d;
}
__device__ __forceinline__ unsigned long long bcast2(float v)
{
    unsigned long long d;
    asm("mov.b64 %0, {%1, %1};" : "=l"(d) : "f"(v));
    return d;
}
__device__ __forceinline__ void unpack2(unsigned long long p, float& lo, float& hi)
{
    asm("mov.b64 {%0, %1}, %2;" : "=f"(lo), "=f"(hi) : "l"(p));
}

// ---------------------------------------------------------------------------
// Weight pre-transpose (merged: ONE launch for all 5 layers).
// w[co][ci][3][3] -> wT[blk][chunk][cc*9+k][WPAD]
// ---------------------------------------------------------------------------
template<int CIN, int COUT, int NCO>
__device__ __forceinline__ void prep_one(const float* __restrict__ w,
                                         float* __restrict__ wT,
                                         int gtid, int nthr)
{
    constexpr int CHUNK = chunk_of(CIN);
    constexpr int WPAD  = NCO + 4;
    constexpr int R     = CHUNK * 9;
    constexpr int NCH   = CIN / CHUNK;
    constexpr int NBLK  = COUT / NCO;
    const int total = NBLK * NCH * R * WPAD;
    for (int idx = gtid; idx < total; idx += nthr) {
        const int co = idx % WPAD;
        int t  = idx / WPAD;
        const int r  = t % R;
        t /= R;
        const int ch  = t % NCH;
        const int blk = t / NCH;
        float v = 0.0f;
        if (co < NCO)
            v = w[(size_t)(blk * NCO + co) * CIN * 9 + ch * R + r];
        wT[idx] = v;
    }
}

__global__ void prep_weights_all(const float* __restrict__ w1,
                                 const float* __restrict__ w2,
                                 const float* __restrict__ w3,
                                 const float* __restrict__ w4,
                                 const float* __restrict__ w5,
                                 float* __restrict__ wT)
{
    const int g = blockIdx.x * blockDim.x + threadIdx.x;
    const int n = gridDim.x * blockDim.x;
    prep_one<3,   64,  64>(w1, wT + WT_OFF1, g, n);
    prep_one<64,  128, 64>(w2, wT + WT_OFF2, g, n);
    prep_one<128, 256, 64>(w3, wT + WT_OFF3, g, n);
    prep_one<256, 512, 64>(w4, wT + WT_OFF4, g, n);
    prep_one<512, 512, 32>(w5, wT + WT_OFF5, g, n);
}

// ---------------------------------------------------------------------------
// 3x3 stride-2 conv + ReLU, SAME padding (JAX: pad_lo=0, pad_hi=1).
//
// v9 = v8 (cp.async double-buffered pipeline + FFMA2 co-pair compute) with
//      CHUNK=8 for CIN>=128 layers (half the chunk barriers; 3 CTAs/SM is
//      still >=2 warps/SMSP, enough to saturate the FFMA2 pipe).
//  - Tile: NCO co x (4 rows x 16 cols); 128 threads.
//  - Accumulators packed over (co, co+1) pairs (32 regs); weight pairs come
//    straight out of LDS.128; one mov.b64 broadcast per input value.
//  - Per-accumulator FMA order (ci ascending x 9 k-pos) identical to v8
//    -> bit-identical output.
// ---------------------------------------------------------------------------
template<int CIN, int COUT, int HIN, int WIN, int NCO>
__global__ __launch_bounds__(128,
    (NCO == 64 ? ((CIN >= 128) ? 3 : 5) : ((CIN >= 128) ? 5 : 8)))
void conv3x3s2_relu(const float* __restrict__ in,
                    const float* __restrict__ wT,
                    float* __restrict__ out)
{
    constexpr int HOUT  = HIN / 2;
    constexpr int WOUT  = WIN / 2;
    constexpr int CHUNK = chunk_of(CIN);              // 8, 4, or 3 (L1)
    constexpr int NCH   = CIN / CHUNK;
    constexpr int NTX   = (WOUT + 15) / 16;
    constexpr int COT   = NCO / 8;                    // co per thread (8 or 4)
    constexpr int CP    = COT / 2;                    // co pairs (4 or 2)
    constexpr int WPAD  = NCO + 4;
    constexpr int R     = CHUNK * 9;
    constexpr int IROW  = 36;                         // padded input row
    constexpr int ITEMS = CHUNK * 9 * 9;              // rows * 9 cp ops
    constexpr int WB    = R * WPAD / 4;               // weight float4 count

    const int bx  = blockIdx.x % NTX;
    const int by  = blockIdx.x / NTX;
    const int ox0 = bx * 16;
    const int oy0 = by * 4;
    const int b   = blockIdx.z;

    __shared__ __align__(16) float s_in[2][CHUNK * 9 * IROW];
    __shared__ __align__(16) float s_w [2][R * WPAD];

    const int tid = threadIdx.x;   // 0..127
    const int tc  = tid >> 4;      // 0..7
    const int tp  = tid & 15;      // 0..15 -> output column within tile

    unsigned long long acc[CP][4] = {};   // [co-pair][row]

    const float* in_b   = in + (size_t)b * CIN * HIN * WIN;
    const float* wT_blk = wT + (size_t)blockIdx.y * NCH * R * WPAD;

    auto load_stage = [&](int ch, int buf) {
        const int ci0 = ch * CHUNK;
#pragma unroll
        for (int i = 0; i < (ITEMS + 127) / 128; i++) {
            const int idx = tid + i * 128;
            if ((ITEMS % 128 == 0) || (idx < ITEMS)) {
                const int c   = idx % 9;
                const int row = idx / 9;        // cc*9 + ly
                const int cc  = row / 9;
                const int ly  = row - cc * 9;
                const int iy  = 2 * oy0 + ly;   // pad_lo = 0
                const float* src = in_b + ((size_t)(ci0 + cc) * HIN + iy) * WIN
                                        + 2 * ox0;
                const uint32_t dst = (uint32_t)__cvta_generic_to_shared(
                    &s_in[buf][row * IROW]);
                const bool rowok = (iy < HIN);
                if (c < 8) {
                    cpa16(dst + c * 16, src + c * 4,
                          rowok && (2 * ox0 + c * 4 < WIN));
                } else {
                    cpa4(dst + 128, src + 32, rowok && (2 * ox0 + 32 < WIN));
                }
            }
        }
        const float* wsrc = wT_blk + (size_t)ch * R * WPAD;
        const uint32_t wdst = (uint32_t)__cvta_generic_to_shared(&s_w[buf][0]);
#pragma unroll
        for (int i = 0; i < (WB + 127) / 128; i++) {
            const int idx = tid + i * 128;
            if ((WB % 128 == 0) || (idx < WB))
                cpa16(wdst + idx * 16, wsrc + idx * 4, true);
        }
    };

    load_stage(0, 0);
    cpa_commit();

    for (int ch = 0; ch < NCH; ch++) {
        cpa_wait0();
        __syncthreads();
        if (ch + 1 < NCH) {
            load_stage(ch + 1, (ch + 1) & 1);
            cpa_commit();
        }

        // ---- compute from buffer ch&1: packed co-pair FFMA2 ----
        const float* pi = &s_in[ch & 1][0] + 2 * tp;
        const float* pw = &s_w [ch & 1][0] + tc * COT;

#pragma unroll 1
        for (int cc = 0; cc < CHUNK; cc++) {
#pragma unroll
            for (int ky = 0; ky < 3; ky++) {
#pragma unroll
                for (int kx = 0; kx < 3; kx++) {
                    const int kp = ky * 3 + kx;
                    // LDS.128 delivers two packed (co,co+1) weight pairs
                    const ulonglong2 wA =
                        *reinterpret_cast<const ulonglong2*>(pw + kp * WPAD);
                    ulonglong2 wB;
                    if constexpr (CP == 4)
                        wB = *reinterpret_cast<const ulonglong2*>(pw + kp * WPAD + 4);
                    // hoisted input broadcasts (4 LDS.32 + 4 mov.b64)
                    unsigned long long iv2[4];
#pragma unroll
                    for (int r = 0; r < 4; r++)
                        iv2[r] = bcast2(pi[(2 * r + ky) * IROW + kx]);
#pragma unroll
                    for (int r = 0; r < 4; r++) {
                        acc[0][r] = fma2(wA.x, iv2[r], acc[0][r]);
                        acc[1][r] = fma2(wA.y, iv2[r], acc[1][r]);
                        if constexpr (CP == 4) {
                            acc[2][r] = fma2(wB.x, iv2[r], acc[2][r]);
                            acc[3][r] = fma2(wB.y, iv2[r], acc[3][r]);
                        }
                    }
                }
            }
            pi += 9 * IROW;    // next input channel
            pw += 9 * WPAD;    // next weight channel
        }
    }

    // ---- epilogue: unpack, ReLU, store ----
    const int co0 = blockIdx.y * NCO;
    float* out_b = out + (size_t)b * COUT * HOUT * WOUT;
    const int ox = ox0 + tp;
    if (ox < WOUT) {
#pragma unroll
        for (int j2 = 0; j2 < CP; j2++) {
            const int co = co0 + tc * COT + 2 * j2;
#pragma unroll
            for (int r = 0; r < 4; r++) {
                const int oy = oy0 + r;
                if (oy < HOUT) {
                    float lo, hi;
                    unpack2(acc[j2][r], lo, hi);
                    out_b[((size_t)co * HOUT + oy) * WOUT + ox]       = fmaxf(lo, 0.0f);
                    out_b[((size_t)(co + 1) * HOUT + oy) * WOUT + ox] = fmaxf(hi, 0.0f);
                }
            }
        }
    }
}

// ---------------------------------------------------------------------------
// 1x1 head conv: pred[b][o][p] = sum_ci h5[b][ci][p] * w[o][ci]
// ---------------------------------------------------------------------------
__global__ void yolo_head_kernel(const float* __restrict__ h5,
                                 const float* __restrict__ w,
                                 float* __restrict__ pred)
{
    const int b = blockIdx.x;
    const int o = blockIdx.y;
    const int p = threadIdx.x;
    if (p >= N_CELLS) return;
    const float* hb = h5 + (size_t)b * 512 * N_CELLS;
    const float* wo = w + o * 512;
    float s = 0.0f;
#pragma unroll 8
    for (int ci = 0; ci < 512; ci++)
        s = fmaf(hb[ci * N_CELLS + p], wo[ci], s);
    pred[(b * HEAD_OUT + o) * N_CELLS + p] = s;
}

// ---------------------------------------------------------------------------
// Decode: sigmoid conf, softmax*conf class scores, box decode + clip.
// ---------------------------------------------------------------------------
__global__ void yolo_decode_kernel(const float* __restrict__ pred,
                                   float* __restrict__ boxes,
                                   float* __restrict__ cls,
                                   float* __restrict__ out)
{
    const int b = blockIdx.x;
    const int p = threadIdx.x;
    if (p >= N_CELLS) return;
    const float* pb = pred + (size_t)b * HEAD_OUT * N_CELLS;

    float conf = 1.0f / (1.0f + expf(-pb[p]));

    float v[NUM_CLS];
    float m = -1e30f;
#pragma unroll
    for (int c = 0; c < NUM_CLS; c++) {
        v[c] = pb[(1 + c) * N_CELLS + p];
        m = fmaxf(m, v[c]);
    }
    float s = 0.0f;
#pragma unroll
    for (int c = 0; c < NUM_CLS; c++) { v[c] = expf(v[c] - m); s += v[c]; }
    float inv = conf / s;

    float tx = pb[21 * N_CELLS + p];
    float ty = pb[22 * N_CELLS + p];
    float tw = pb[23 * N_CELLS + p];
    float th = pb[24 * N_CELLS + p];

    float gx = (float)(p % WS_GRID);
    float gy = (float)(p / WS_GRID);
    float cx = (1.0f / (1.0f + expf(-tx)) + gx) * STRIDE_F;
    float cy = (1.0f / (1.0f + expf(-ty)) + gy) * STRIDE_F;
    float bw = expf(tw) * STRIDE_F;
    float bh = expf(th) * STRIDE_F;

    float x1 = (cx - bw * 0.5f) / 448.0f;
    float y1 = (cy - bh * 0.5f) / 448.0f;
    float x2 = (cx + bw * 0.5f) / 448.0f;
    float y2 = (cy + bh * 0.5f) / 448.0f;
    x1 = fminf(fmaxf(x1, 0.0f), 1.0f);
    y1 = fminf(fmaxf(y1, 0.0f), 1.0f);
    x2 = fminf(fmaxf(x2, 0.0f), 1.0f);
    y2 = fminf(fmaxf(y2, 0.0f), 1.0f);

    const int row = b * N_CELLS + p;
    boxes[row * 4 + 0] = x1;
    boxes[row * 4 + 1] = y1;
    boxes[row * 4 + 2] = x2;
    boxes[row * 4 + 3] = y2;
    out[row * 24 + 0] = x1;
    out[row * 24 + 1] = y1;
    out[row * 24 + 2] = x2;
    out[row * 24 + 3] = y2;
#pragma unroll
    for (int c = 0; c < NUM_CLS; c++)
        cls[row * NUM_CLS + c] = v[c] * inv;
}

// ---------------------------------------------------------------------------
// Per-(batch, class) greedy NMS. One block per problem.
// ---------------------------------------------------------------------------
__global__ void yolo_nms_kernel(const float* __restrict__ boxes,
                                const float* __restrict__ cls,
                                float* __restrict__ out)
{
    const int c = blockIdx.x;   // class
    const int b = blockIdx.y;   // batch
    const int t = threadIdx.x;

    __shared__ float ss[N_CELLS];
    __shared__ float sx1[N_CELLS], sy1[N_CELLS], sx2[N_CELLS], sy2[N_CELLS];
    __shared__ float sa[N_CELLS];
    __shared__ int   sorder[N_CELLS];
    __shared__ int   skeep[N_CELLS];

    if (t < N_CELLS) {
        const int row = b * N_CELLS + t;
        ss[t] = cls[row * NUM_CLS + c];
        float x1 = boxes[row * 4 + 0];
        float y1 = boxes[row * 4 + 1];
        float x2 = boxes[row * 4 + 2];
        float y2 = boxes[row * 4 + 3];
        sx1[t] = x1; sy1[t] = y1; sx2[t] = x2; sy2[t] = y2;
        sa[t] = fmaxf(x2 - x1, 0.0f) * fmaxf(y2 - y1, 0.0f);
    }
    __syncthreads();

    if (t < N_CELLS) {   // stable descending rank (== stable argsort of -s)
        float sp = ss[t];
        int r = 0;
        for (int q = 0; q < N_CELLS; q++) {
            float sq = ss[q];
            r += (sq > sp) || (sq == sp && q < t);
        }
        sorder[r] = t;
        skeep[r]  = (sp > CONF_TH) ? 1 : 0;
    }
    __syncthreads();

    int pj = 0;
    float bx1 = 0.f, by1 = 0.f, bx2 = 0.f, by2 = 0.f, ba = 0.f;
    if (t < N_CELLS) {
        pj  = sorder[t];
        bx1 = sx1[pj]; by1 = sy1[pj]; bx2 = sx2[pj]; by2 = sy2[pj]; ba = sa[pj];
    }

    for (int i = 0; i < N_CELLS - 1; i++) {
        if (skeep[i]) {
            int pi = sorder[i];
            float ax1 = sx1[pi], ay1 = sy1[pi];
            float ax2 = sx2[pi], ay2 = sy2[pi];
            float aa  = sa[pi];
            if (t < N_CELLS && t > i && skeep[t]) {
                float ix1 = fmaxf(ax1, bx1), iy1 = fmaxf(ay1, by1);
                float ix2 = fminf(ax2, bx2), iy2 = fminf(ay2, by2);
                float inter = fmaxf(ix2 - ix1, 0.0f) * fmaxf(iy2 - iy1, 0.0f);
                float iou = inter / (aa + ba - inter + 1e-14f);
                if (iou > NMS_TH) skeep[t] = 0;
            }
        }
        __syncthreads();
    }

    if (t < N_CELLS) {
        const int row = b * N_CELLS + pj;
        out[row * 24 + 4 + c] = ss[pj] * (skeep[t] ? 1.0f : 0.0f);
    }
}

// ---------------------------------------------------------------------------
// Launch
// ---------------------------------------------------------------------------
extern "C" void kernel_launch(void* const* d_in, const int* in_sizes, int n_in,
                              void* d_out, int out_size)
{
    const float* x  = (const float*)d_in[0];
    const float* w1 = (const float*)d_in[1];
    const float* w2 = (const float*)d_in[2];
    const float* w3 = (const float*)d_in[3];
    const float* w4 = (const float*)d_in[4];
    const float* w5 = (const float*)d_in[5];
    const float* wh = (const float*)d_in[6];
    float* out = (float*)d_out;

    float *bufA, *bufB, *pred, *boxes, *cls, *wT;
    cudaGetSymbolAddress((void**)&bufA, g_bufA);
    cudaGetSymbolAddress((void**)&bufB, g_bufB);
    cudaGetSymbolAddress((void**)&pred, g_pred);
    cudaGetSymbolAddress((void**)&boxes, g_boxes);
    cudaGetSymbolAddress((void**)&cls, g_cls);
    cudaGetSymbolAddress((void**)&wT, g_wT);

    float* h1 = bufA;
    float* h2 = bufB;
    float* h3 = bufA;
    float* h4 = bufB;
    float* h5 = bufA;

    // ---- weight pre-transpose: single merged launch ----
    prep_weights_all<<<1024, 256>>>(w1, w2, w3, w4, w5, wT);

    {   // L1: 3 -> 64, 448 -> 224
        constexpr int NTX = (224 + 15) / 16, NTY = (224 + 3) / 4;
        conv3x3s2_relu<3, 64, 448, 448, 64>
            <<<dim3(NTX * NTY, 1, BATCH), 128>>>(x, wT + WT_OFF1, h1);
    }
    {   // L2: 64 -> 128, 224 -> 112  (CHUNK=4, 5 CTAs/SM)
        constexpr int NTX = (112 + 15) / 16, NTY = (112 + 3) / 4;
        conv3x3s2_relu<64, 128, 224, 224, 64>
            <<<dim3(NTX * NTY, 2, BATCH), 128>>>(h1, wT + WT_OFF2, h2);
    }
    {   // L3: 128 -> 256, 112 -> 56  (CHUNK=8)
        constexpr int NTX = (56 + 15) / 16, NTY = (56 + 3) / 4;
        conv3x3s2_relu<128, 256, 112, 112, 64>
            <<<dim3(NTX * NTY, 4, BATCH), 128>>>(h2, wT + WT_OFF3, h3);
    }
    {   // L4: 256 -> 512, 56 -> 28  (CHUNK=8)
        constexpr int NTX = (28 + 15) / 16, NTY = (28 + 3) / 4;
        conv3x3s2_relu<256, 512, 56, 56, 64>
            <<<dim3(NTX * NTY, 8, BATCH), 128>>>(h3, wT + WT_OFF4, h4);
    }
    {   // L5: 512 -> 512, 28 -> 14  (CHUNK=8, NCO=32 -> 512 CTAs)
        constexpr int NTX = (14 + 15) / 16, NTY = (14 + 3) / 4;
        conv3x3s2_relu<512, 512, 28, 28, 32>
            <<<dim3(NTX * NTY, 16, BATCH), 128>>>(h4, wT + WT_OFF5, h5);
    }

    yolo_head_kernel<<<dim3(BATCH, HEAD_OUT), 224>>>(h5, wh, pred);
    yolo_decode_kernel<<<BATCH, 224>>>(pred, boxes, cls, out);
    yolo_nms_kernel<<<dim3(NUM_CLS, BATCH), 224>>>(boxes, cls, out);
}